// round 1
// baseline (speedup 1.0000x reference)
#include <cuda_runtime.h>
#include <math.h>

#define Bb 8
#define Mm 2048
#define Dd 128
#define Hh 8
#define HDIM 16
#define Vv 32
#define TOK (Bb*Mm)          // 16384
#define SLAB (Mm*Dd)         // 262144 elements per batch slab

// ----------------------------- scratch (static device globals) ---------------
__device__ float g_x0[TOK*Dd];   // normalized embedding (residual base)
__device__ float g_q [TOK*Dd];
__device__ float g_k [TOK*Dd];
__device__ float g_v [TOK*Dd];
__device__ float g_qp[TOK*Dd];
__device__ float g_kp[TOK*Dd];
__device__ float g_vp[TOK*Dd];
__device__ float g_att[TOK*Dd];
__device__ float g_x1[TOK*Dd];
__device__ float g_x2[TOK*Dd];
__device__ float g_x3[TOK*Dd];
__device__ float g_cos[Mm*64];
__device__ float g_sin[Mm*64];
__device__ float g_part[Bb*128];
__device__ float g_inv[Bb];
__device__ float g_losspart[64];

// ----------------------------- RoPE tables -----------------------------------
__global__ void k_rope_tables() {
    int i   = threadIdx.x;        // 0..63
    int pos = blockIdx.x;         // 0..2047
    float base = powf(10000.0f, -2.0f * ((float)i - 1.0f) / 128.0f);
    float ang  = (float)pos * base;
    float s, c;
    sincosf(ang, &s, &c);
    g_cos[pos*64 + i] = c;
    g_sin[pos*64 + i] = s;
}

// ----------------------------- embedding gather + ssq partials ---------------
__global__ void __launch_bounds__(256) k_embed(const int* __restrict__ idx,
                                               const float* __restrict__ emb) {
    int b   = blockIdx.x;         // batch
    int seg = blockIdx.y;         // 0..127
    int tid = threadIdx.x;        // 256
    int tok0 = seg * 16;          // 16 tokens = 2048 elems per block
    float ss = 0.f;
    #pragma unroll
    for (int e = 0; e < 8; e++) {
        int li = tid + e * 256;               // 0..2047
        int t  = tok0 + (li >> 7);
        int d  = li & 127;
        int row = idx[b*Mm + t];
        float vv = emb[row*Dd + d];
        g_x0[((size_t)(b*Mm + t))*Dd + d] = vv;
        ss += vv * vv;
    }
    __shared__ float red[256];
    red[tid] = ss; __syncthreads();
    for (int s = 128; s > 0; s >>= 1) {
        if (tid < s) red[tid] += red[tid + s];
        __syncthreads();
    }
    if (tid == 0) g_part[b*128 + seg] = red[0];
}

// ----------------------------- ssq partials of an arbitrary buffer -----------
__global__ void __launch_bounds__(256) k_ssq(const float* __restrict__ x) {
    int b   = blockIdx.x;
    int seg = blockIdx.y;
    int tid = threadIdx.x;
    const float* p = x + (size_t)b*SLAB + seg*2048;
    float ss = 0.f;
    #pragma unroll
    for (int e = 0; e < 8; e++) {
        float vv = p[tid + e*256];
        ss += vv * vv;
    }
    __shared__ float red[256];
    red[tid] = ss; __syncthreads();
    for (int s = 128; s > 0; s >>= 1) {
        if (tid < s) red[tid] += red[tid + s];
        __syncthreads();
    }
    if (tid == 0) g_part[b*128 + seg] = red[0];
}

// ----------------------------- finalize per-batch inverse RMS factor ---------
__global__ void k_inv() {
    int b = blockIdx.x;
    int tid = threadIdx.x;   // 128
    __shared__ float red[128];
    red[tid] = g_part[b*128 + tid]; __syncthreads();
    for (int s = 64; s > 0; s >>= 1) {
        if (tid < s) red[tid] += red[tid + s];
        __syncthreads();
    }
    // x / fr = x * sqrt(M*D) / sqrt(ssq);  sqrt(262144)=512 exactly
    if (tid == 0) g_inv[b] = 512.0f / sqrtf(red[0]);
}

// ----------------------------- apply norm + scale -----------------------------
__global__ void __launch_bounds__(256) k_norm(const float* __restrict__ x,
                                              const float* __restrict__ scale,
                                              float* __restrict__ y) {
    int i = blockIdx.x * 256 + threadIdx.x;   // < TOK*Dd = 2097152
    int b = i >> 18;                          // / 262144
    int r = i & (SLAB - 1);
    int m = r >> 7;
    int d = r & 127;
    y[i] = x[i] * g_inv[b] * scale[m*Dd + d];
}

// ----------------------------- generic GEMM: C = A(16384x128) @ W(Ncols x 128)^T
// epilogue: +bias, optional relu, optional +resid
__global__ void __launch_bounds__(128) k_gemm(const float* __restrict__ A,
                                              const float* __restrict__ W,
                                              const float* __restrict__ bias,
                                              const float* __restrict__ resid,
                                              float* __restrict__ C,
                                              int Ncols, int relu) {
    __shared__ float As[64][65];
    __shared__ float Ws[64][65];
    int tid = threadIdx.x;
    int rowBase = blockIdx.x * 64;
    int colBase = blockIdx.y * 64;
    int tr = (tid >> 4) * 8;     // 0..56
    int tc = (tid & 15) * 4;     // 0..60

    float acc[32];
    #pragma unroll
    for (int i = 0; i < 32; i++) acc[i] = 0.f;

    for (int kc = 0; kc < 128; kc += 64) {
        #pragma unroll
        for (int e = 0; e < 8; e++) {
            int fi  = tid + e * 128;        // 0..1023
            int row = fi >> 4;
            int kq  = fi & 15;
            float4 va = *(const float4*)(A + (size_t)(rowBase + row)*128 + kc + kq*4);
            As[kq*4+0][row] = va.x; As[kq*4+1][row] = va.y;
            As[kq*4+2][row] = va.z; As[kq*4+3][row] = va.w;
            int gn = colBase + row;
            float4 vw = (gn < Ncols) ? *(const float4*)(W + (size_t)gn*128 + kc + kq*4)
                                     : make_float4(0.f, 0.f, 0.f, 0.f);
            Ws[kq*4+0][row] = vw.x; Ws[kq*4+1][row] = vw.y;
            Ws[kq*4+2][row] = vw.z; Ws[kq*4+3][row] = vw.w;
        }
        __syncthreads();
        #pragma unroll 16
        for (int k = 0; k < 64; k++) {
            float a[8], bf[4];
            #pragma unroll
            for (int i = 0; i < 8; i++) a[i] = As[k][tr + i];
            #pragma unroll
            for (int j = 0; j < 4; j++) bf[j] = Ws[k][tc + j];
            #pragma unroll
            for (int i = 0; i < 8; i++)
                #pragma unroll
                for (int j = 0; j < 4; j++)
                    acc[i*4 + j] += a[i] * bf[j];
        }
        __syncthreads();
    }

    #pragma unroll
    for (int i = 0; i < 8; i++) {
        int r = rowBase + tr + i;
        #pragma unroll
        for (int j = 0; j < 4; j++) {
            int n = colBase + tc + j;
            if (n < Ncols) {
                float vv = acc[i*4 + j];
                if (bias)  vv += bias[n];
                if (relu)  vv = fmaxf(vv, 0.f);
                if (resid) vv += resid[(size_t)r*Ncols + n];
                C[(size_t)r*Ncols + n] = vv;
            }
        }
    }
}

// ----------------------------- apply RoPE in place to g_q, g_k, g_v ----------
__global__ void __launch_bounds__(256) k_rope() {
    int id = blockIdx.x * 256 + threadIdx.x;   // < 3*TOK*64 = 3145728
    int w  = id / (TOK * 64);
    int r  = id % (TOK * 64);
    int tok = r >> 6;
    int i   = r & 63;
    int m   = tok & (Mm - 1);
    float* arr = (w == 0) ? g_q : ((w == 1) ? g_k : g_v);
    float c = g_cos[m*64 + i];
    float s = g_sin[m*64 + i];
    float2 t = *(float2*)(arr + (size_t)tok*Dd + 2*i);
    float2 o;
    o.x =  t.x * c + t.y * s;
    o.y = -t.x * s + t.y * c;
    *(float2*)(arr + (size_t)tok*Dd + 2*i) = o;
}

// ----------------------------- causal flash attention ------------------------
// grid: (8 q-tiles of 256, 64 bh). 1 query row per thread, 32-key smem tiles.
__global__ void __launch_bounds__(256) k_attn() {
    int qt = blockIdx.x;
    int bh = blockIdx.y;
    int b = bh >> 3, h = bh & 7;
    int tid = threadIdx.x;
    int q = qt * 256 + tid;

    const float* qrow = g_qp + ((size_t)(b*Mm + q))*Dd + h*HDIM;
    float qv[16];
    #pragma unroll
    for (int t4 = 0; t4 < 4; t4++) {
        float4 tmp = *(const float4*)(qrow + t4*4);
        qv[t4*4+0] = tmp.x; qv[t4*4+1] = tmp.y;
        qv[t4*4+2] = tmp.z; qv[t4*4+3] = tmp.w;
    }
    float acc[16];
    #pragma unroll
    for (int i = 0; i < 16; i++) acc[i] = 0.f;
    float mrun = -1e30f, lsum = 0.f;

    __shared__ float Ks[32][16];
    __shared__ float Vs[32][16];

    int nk = (qt + 1) * 8;
    for (int kt = 0; kt < nk; kt++) {
        int kb = kt * 32;
        __syncthreads();
        {
            int lt = tid & 127;
            int row = lt >> 2, quad = lt & 3;
            const float* src = ((tid < 128) ? g_kp : g_vp)
                             + ((size_t)(b*Mm + kb + row))*Dd + h*HDIM + quad*4;
            float4 vv = *(const float4*)src;
            float* dst = (tid < 128) ? &Ks[row][quad*4] : &Vs[row][quad*4];
            *(float4*)dst = vv;
        }
        __syncthreads();

        float s[32];
        float tmax = -1e30f;
        #pragma unroll
        for (int j = 0; j < 32; j++) {
            const float4* kr = (const float4*)&Ks[j][0];
            float4 k0 = kr[0], k1 = kr[1], k2 = kr[2], k3 = kr[3];
            float d = qv[0]*k0.x + qv[1]*k0.y + qv[2]*k0.z + qv[3]*k0.w
                    + qv[4]*k1.x + qv[5]*k1.y + qv[6]*k1.z + qv[7]*k1.w
                    + qv[8]*k2.x + qv[9]*k2.y + qv[10]*k2.z + qv[11]*k2.w
                    + qv[12]*k3.x + qv[13]*k3.y + qv[14]*k3.z + qv[15]*k3.w;
            d *= 0.25f;                     // 1/sqrt(HD=16)
            s[j] = ((kb + j) <= q) ? d : -1e30f;
            tmax = fmaxf(tmax, s[j]);
        }
        if (tmax > -1e29f) {
            float mnew  = fmaxf(mrun, tmax);
            float alpha = __expf(mrun - mnew);   // underflows to 0 on first tile
            lsum *= alpha;
            #pragma unroll
            for (int i = 0; i < 16; i++) acc[i] *= alpha;
            #pragma unroll
            for (int j = 0; j < 32; j++) {
                float p = (s[j] > -1e29f) ? __expf(s[j] - mnew) : 0.f;
                lsum += p;
                const float4* vr = (const float4*)&Vs[j][0];
                float4 v0 = vr[0], v1 = vr[1], v2 = vr[2], v3 = vr[3];
                acc[0]  += p*v0.x; acc[1]  += p*v0.y; acc[2]  += p*v0.z; acc[3]  += p*v0.w;
                acc[4]  += p*v1.x; acc[5]  += p*v1.y; acc[6]  += p*v1.z; acc[7]  += p*v1.w;
                acc[8]  += p*v2.x; acc[9]  += p*v2.y; acc[10] += p*v2.z; acc[11] += p*v2.w;
                acc[12] += p*v3.x; acc[13] += p*v3.y; acc[14] += p*v3.z; acc[15] += p*v3.w;
            }
            mrun = mnew;
        }
    }

    float inv = 1.f / lsum;
    float* orow = g_att + ((size_t)(b*Mm + q))*Dd + h*HDIM;
    #pragma unroll
    for (int t4 = 0; t4 < 4; t4++) {
        float4 o;
        o.x = acc[t4*4+0]*inv; o.y = acc[t4*4+1]*inv;
        o.z = acc[t4*4+2]*inv; o.w = acc[t4*4+3]*inv;
        *(float4*)(orow + t4*4) = o;
    }
}

// ----------------------------- loss ------------------------------------------
__global__ void __launch_bounds__(256) k_loss(const int* __restrict__ tgt,
                                              const float* __restrict__ logits) {
    int tok = blockIdx.x * 256 + threadIdx.x;   // 64 blocks
    const float* lp = logits + (size_t)tok * Vv;
    float vals[32];
    float mx = -1e30f;
    #pragma unroll
    for (int e = 0; e < 8; e++) {
        float4 v = *(const float4*)(lp + e*4);
        vals[e*4+0] = v.x; vals[e*4+1] = v.y; vals[e*4+2] = v.z; vals[e*4+3] = v.w;
        mx = fmaxf(mx, fmaxf(fmaxf(v.x, v.y), fmaxf(v.z, v.w)));
    }
    float se = 0.f;
    #pragma unroll
    for (int j = 0; j < 32; j++) se += expf(vals[j] - mx);
    float tv = lp[tgt[tok]];
    float nll = -(tv - mx - logf(se));

    __shared__ float red[256];
    red[threadIdx.x] = nll; __syncthreads();
    for (int s = 128; s > 0; s >>= 1) {
        if (threadIdx.x < s) red[threadIdx.x] += red[threadIdx.x + s];
        __syncthreads();
    }
    if (threadIdx.x == 0) g_losspart[blockIdx.x] = red[0];
}

__global__ void k_loss2(float* out) {
    __shared__ float red[64];
    red[threadIdx.x] = g_losspart[threadIdx.x]; __syncthreads();
    for (int s = 32; s > 0; s >>= 1) {
        if (threadIdx.x < s) red[threadIdx.x] += red[threadIdx.x + s];
        __syncthreads();
    }
    if (threadIdx.x == 0) out[0] = red[0] / (float)TOK;
}

// ----------------------------- host driver -----------------------------------
extern "C" void kernel_launch(void* const* d_in, const int* in_sizes, int n_in,
                              void* d_out, int out_size) {
    const int*   idx = (const int*)  d_in[0];
    const int*   tgt = (const int*)  d_in[1];
    const float* emb = (const float*)d_in[2];
    const float* rms = (const float*)d_in[3];
    const float* Wq  = (const float*)d_in[4];
    const float* Wk  = (const float*)d_in[5];
    const float* Wv  = (const float*)d_in[6];
    const float* inw = (const float*)d_in[7];
    const float* inb = (const float*)d_in[8];
    const float* opw = (const float*)d_in[9];
    const float* opb = (const float*)d_in[10];
    const float* lw  = (const float*)d_in[11];
    const float* lb  = (const float*)d_in[12];
    const float* ow  = (const float*)d_in[13];
    const float* ob  = (const float*)d_in[14];
    float* out = (float*)d_out;

    float *x0, *q, *k, *v, *qp, *kp, *vp, *att, *x1, *x2, *x3;
    cudaGetSymbolAddress((void**)&x0,  g_x0);
    cudaGetSymbolAddress((void**)&q,   g_q);
    cudaGetSymbolAddress((void**)&k,   g_k);
    cudaGetSymbolAddress((void**)&v,   g_v);
    cudaGetSymbolAddress((void**)&qp,  g_qp);
    cudaGetSymbolAddress((void**)&kp,  g_kp);
    cudaGetSymbolAddress((void**)&vp,  g_vp);
    cudaGetSymbolAddress((void**)&att, g_att);
    cudaGetSymbolAddress((void**)&x1,  g_x1);
    cudaGetSymbolAddress((void**)&x2,  g_x2);
    cudaGetSymbolAddress((void**)&x3,  g_x3);

    k_rope_tables<<<Mm, 64>>>();
    k_embed<<<dim3(Bb, 128), 256>>>(idx, emb);
    k_inv<<<Bb, 128>>>();
    k_norm<<<TOK*Dd/256, 256>>>(x0, rms, x0);

    k_gemm<<<dim3(256, 2), 128>>>(x0, Wq, nullptr, nullptr, q, 128, 0);
    k_gemm<<<dim3(256, 2), 128>>>(x0, Wk, nullptr, nullptr, k, 128, 0);
    k_gemm<<<dim3(256, 2), 128>>>(x0, Wv, nullptr, nullptr, v, 128, 0);

    k_rope<<<(3*TOK*64)/256, 256>>>();

    k_gemm<<<dim3(256, 2), 128>>>(q, inw,            inb,        nullptr, qp, 128, 0);
    k_gemm<<<dim3(256, 2), 128>>>(k, inw + Dd*Dd,    inb + Dd,   nullptr, kp, 128, 0);
    k_gemm<<<dim3(256, 2), 128>>>(v, inw + 2*Dd*Dd,  inb + 2*Dd, nullptr, vp, 128, 0);

    k_attn<<<dim3(8, 64), 256>>>();

    k_gemm<<<dim3(256, 2), 128>>>(att, opw, opb, x0, x1, 128, 0);

    k_ssq<<<dim3(Bb, 128), 256>>>(x1);
    k_inv<<<Bb, 128>>>();
    k_norm<<<TOK*Dd/256, 256>>>(x1, rms, x2);

    k_gemm<<<dim3(256, 2), 128>>>(x2, lw, lb, x2, x3, 128, 1);   // relu + residual
    k_gemm<<<dim3(256, 1), 128>>>(x3, ow, ob, nullptr, out, Vv, 0);

    k_loss<<<TOK/256, 256>>>(tgt, out);
    if (out_size > TOK*Vv) k_loss2<<<1, 64>>>(out + (size_t)TOK*Vv);
}

// round 3
// speedup vs baseline: 1.0790x; 1.0790x over previous
#include <cuda_runtime.h>
#include <math.h>
#include <stdint.h>

#define Bb 8
#define Mm 2048
#define Dd 128
#define HDIM 16
#define Vv 32
#define TOK (Bb*Mm)          // 16384
#define SLAB (Mm*Dd)         // 262144 elements per batch slab

// ----------------------------- scratch (static device globals) ---------------
__device__ float g_x0[TOK*Dd];
__device__ float g_q [TOK*Dd];
__device__ float g_k [TOK*Dd];
__device__ float g_v [TOK*Dd];
__device__ float g_qp[TOK*Dd];
__device__ float g_kp[TOK*Dd];
__device__ float g_vp[TOK*Dd];
__device__ float g_att[TOK*Dd];
__device__ float g_x1[TOK*Dd];
__device__ float g_x2[TOK*Dd];
__device__ float g_x3[TOK*Dd];
__device__ float g_cos[Mm*64];
__device__ float g_sin[Mm*64];
__device__ float g_part[Bb*128];
__device__ float g_inv[Bb];
__device__ float g_losspart[64];

// ----------------------------- helpers ----------------------------------------
__device__ __forceinline__ float f2tf32(float v) {
    float r; asm("cvt.rna.tf32.f32 %0, %1;" : "=f"(r) : "f"(v)); return r;
}
__device__ __forceinline__ void mma_tf32(float c[4], const uint32_t a[4],
                                         const uint32_t b[2]) {
    asm volatile(
        "mma.sync.aligned.m16n8k8.row.col.f32.tf32.tf32.f32 "
        "{%0,%1,%2,%3}, {%4,%5,%6,%7}, {%8,%9}, {%0,%1,%2,%3};"
        : "+f"(c[0]), "+f"(c[1]), "+f"(c[2]), "+f"(c[3])
        : "r"(a[0]), "r"(a[1]), "r"(a[2]), "r"(a[3]), "r"(b[0]), "r"(b[1]));
}
__device__ __forceinline__ void split(float v, uint32_t& hi, uint32_t& lo) {
    float h = f2tf32(v);
    float l = f2tf32(v - h);
    hi = __float_as_uint(h);
    lo = __float_as_uint(l);
}

// ----------------------------- tensor-core tf32 GEMM --------------------------
// C[16384 x Ncols] = A[16384 x 128] @ W[Ncols x 128]^T (+bias)(relu)(rope)(+resid)
// CTA tile M=128, N=NT; 8 warps in 4x2; 3xTF32 decomposition.
// flags: bit0 = relu, bit1 = rope
#define PITCH 132
template <int NT>
__global__ void __launch_bounds__(256, 2) k_mma_gemm(
    const float* __restrict__ A, const float* __restrict__ W,
    const float* __restrict__ bias, const float* __restrict__ resid,
    float* __restrict__ C, int ldc, int flags)
{
    extern __shared__ float sm[];
    float* As = sm;                    // [128][PITCH]
    float* Ws = sm + 128 * PITCH;      // [NT][PITCH]
    constexpr int TN = NT / 16;        // n-tiles (8 wide) per warp

    int tid = threadIdx.x;
    int rowBase = blockIdx.x * 128;
    int colBase = blockIdx.y * NT;

    // ---- stage A tile [128 x 128]
    #pragma unroll
    for (int i = 0; i < 16; i++) {
        int f = tid + i * 256;               // 0..4095 float4s
        int row = f >> 5, q = f & 31;
        float4 v = *(const float4*)(A + (size_t)(rowBase + row) * 128 + q * 4);
        *(float4*)(As + row * PITCH + q * 4) = v;
    }
    // ---- stage W tile [NT x 128]
    #pragma unroll
    for (int i = 0; i < NT / 8; i++) {
        int f = tid + i * 256;
        int row = f >> 5, q = f & 31;
        float4 v = *(const float4*)(W + (size_t)(colBase + row) * 128 + q * 4);
        *(float4*)(Ws + row * PITCH + q * 4) = v;
    }
    __syncthreads();

    int w = tid >> 5, lane = tid & 31;
    int g = lane >> 2, tg = lane & 3;
    int mBase = (w & 3) * 32;
    int nBase = (w >> 2) * (NT / 2);

    float acc[2][TN][4];
    #pragma unroll
    for (int tm = 0; tm < 2; tm++)
        #pragma unroll
        for (int tn = 0; tn < TN; tn++)
            #pragma unroll
            for (int e = 0; e < 4; e++) acc[tm][tn][e] = 0.f;

    #pragma unroll 4
    for (int ks = 0; ks < 16; ks++) {
        int k0 = ks * 8;
        uint32_t ahi[2][4], alo[2][4];
        #pragma unroll
        for (int tm = 0; tm < 2; tm++) {
            const float* p  = As + (mBase + tm * 16 + g) * PITCH + k0 + tg;
            const float* p8 = p + 8 * PITCH;
            split(p [0], ahi[tm][0], alo[tm][0]);   // (row g,    col tg)
            split(p8[0], ahi[tm][1], alo[tm][1]);   // (row g+8,  col tg)
            split(p [4], ahi[tm][2], alo[tm][2]);   // (row g,    col tg+4)
            split(p8[4], ahi[tm][3], alo[tm][3]);   // (row g+8,  col tg+4)
        }
        uint32_t bhi[TN][2], blo[TN][2];
        #pragma unroll
        for (int tn = 0; tn < TN; tn++) {
            const float* p = Ws + (nBase + tn * 8 + g) * PITCH + k0 + tg;
            split(p[0], bhi[tn][0], blo[tn][0]);    // (k tg,   n g)
            split(p[4], bhi[tn][1], blo[tn][1]);    // (k tg+4, n g)
        }
        #pragma unroll
        for (int tm = 0; tm < 2; tm++)
            #pragma unroll
            for (int tn = 0; tn < TN; tn++) {
                mma_tf32(acc[tm][tn], ahi[tm], bhi[tn]);
                mma_tf32(acc[tm][tn], alo[tm], bhi[tn]);
                mma_tf32(acc[tm][tn], ahi[tm], blo[tn]);
            }
    }

    // ---- epilogue
    #pragma unroll
    for (int tm = 0; tm < 2; tm++) {
        #pragma unroll
        for (int tn = 0; tn < TN; tn++) {
            int col = colBase + nBase + tn * 8 + tg * 2;      // even
            #pragma unroll
            for (int half = 0; half < 2; half++) {
                int row = rowBase + mBase + tm * 16 + g + half * 8;
                float v0 = acc[tm][tn][half * 2 + 0];
                float v1 = acc[tm][tn][half * 2 + 1];
                if (bias) { v0 += bias[col]; v1 += bias[col + 1]; }
                if (flags & 1) { v0 = fmaxf(v0, 0.f); v1 = fmaxf(v1, 0.f); }
                if (flags & 2) {
                    int m = row & (Mm - 1);
                    int i = col >> 1;
                    float cc = g_cos[m * 64 + i];
                    float ss = g_sin[m * 64 + i];
                    float te = v0, to = v1;
                    v0 =  te * cc + to * ss;
                    v1 = -te * ss + to * cc;
                }
                if (resid) {
                    v0 += resid[(size_t)row * ldc + col];
                    v1 += resid[(size_t)row * ldc + col + 1];
                }
                float2 o; o.x = v0; o.y = v1;
                *(float2*)(C + (size_t)row * ldc + col) = o;
            }
        }
    }
}

// ----------------------------- RoPE tables -----------------------------------
__global__ void k_rope_tables() {
    int i   = threadIdx.x;        // 0..63
    int pos = blockIdx.x;         // 0..2047
    float base = powf(10000.0f, -2.0f * ((float)i - 1.0f) / 128.0f);
    float ang  = (float)pos * base;
    float s, c;
    sincosf(ang, &s, &c);
    g_cos[pos*64 + i] = c;
    g_sin[pos*64 + i] = s;
}

// ----------------------------- embedding gather + ssq partials ---------------
__global__ void __launch_bounds__(256) k_embed(const int* __restrict__ idx,
                                               const float* __restrict__ emb) {
    int b   = blockIdx.x;
    int seg = blockIdx.y;
    int tid = threadIdx.x;
    int tok0 = seg * 16;
    float ss = 0.f;
    #pragma unroll
    for (int e = 0; e < 8; e++) {
        int li = tid + e * 256;
        int t  = tok0 + (li >> 7);
        int d  = li & 127;
        int row = idx[b*Mm + t];
        float vv = emb[row*Dd + d];
        g_x0[((size_t)(b*Mm + t))*Dd + d] = vv;
        ss += vv * vv;
    }
    __shared__ float red[256];
    red[tid] = ss; __syncthreads();
    for (int s = 128; s > 0; s >>= 1) {
        if (tid < s) red[tid] += red[tid + s];
        __syncthreads();
    }
    if (tid == 0) g_part[b*128 + seg] = red[0];
}

// ----------------------------- ssq partials -----------------------------------
__global__ void __launch_bounds__(256) k_ssq(const float* __restrict__ x) {
    int b   = blockIdx.x;
    int seg = blockIdx.y;
    int tid = threadIdx.x;
    const float* p = x + (size_t)b*SLAB + seg*2048;
    float ss = 0.f;
    #pragma unroll
    for (int e = 0; e < 8; e++) {
        float vv = p[tid + e*256];
        ss += vv * vv;
    }
    __shared__ float red[256];
    red[tid] = ss; __syncthreads();
    for (int s = 128; s > 0; s >>= 1) {
        if (tid < s) red[tid] += red[tid + s];
        __syncthreads();
    }
    if (tid == 0) g_part[b*128 + seg] = red[0];
}

__global__ void k_inv() {
    int b = blockIdx.x;
    int tid = threadIdx.x;
    __shared__ float red[128];
    red[tid] = g_part[b*128 + tid]; __syncthreads();
    for (int s = 64; s > 0; s >>= 1) {
        if (tid < s) red[tid] += red[tid + s];
        __syncthreads();
    }
    if (tid == 0) g_inv[b] = 512.0f / sqrtf(red[0]);
}

__global__ void __launch_bounds__(256) k_norm(const float* __restrict__ x,
                                              const float* __restrict__ scale,
                                              float* __restrict__ y) {
    int i = blockIdx.x * 256 + threadIdx.x;
    int b = i >> 18;
    int r = i & (SLAB - 1);
    int m = r >> 7;
    int d = r & 127;
    y[i] = x[i] * g_inv[b] * scale[m*Dd + d];
}

// ----------------------------- causal flash attention ------------------------
__global__ void __launch_bounds__(256) k_attn() {
    int qt = blockIdx.x;
    int bh = blockIdx.y;
    int b = bh >> 3, h = bh & 7;
    int tid = threadIdx.x;
    int q = qt * 256 + tid;

    const float* qrow = g_qp + ((size_t)(b*Mm + q))*Dd + h*HDIM;
    float qv[16];
    #pragma unroll
    for (int t4 = 0; t4 < 4; t4++) {
        float4 tmp = *(const float4*)(qrow + t4*4);
        qv[t4*4+0] = tmp.x; qv[t4*4+1] = tmp.y;
        qv[t4*4+2] = tmp.z; qv[t4*4+3] = tmp.w;
    }
    float acc[16];
    #pragma unroll
    for (int i = 0; i < 16; i++) acc[i] = 0.f;
    float mrun = -1e30f, lsum = 0.f;

    __shared__ float Ks[32][16];
    __shared__ float Vs[32][16];

    int nk = (qt + 1) * 8;
    for (int kt = 0; kt < nk; kt++) {
        int kb = kt * 32;
        __syncthreads();
        {
            int lt = tid & 127;
            int row = lt >> 2, quad = lt & 3;
            const float* src = ((tid < 128) ? g_kp : g_vp)
                             + ((size_t)(b*Mm + kb + row))*Dd + h*HDIM + quad*4;
            float4 vv = *(const float4*)src;
            float* dst = (tid < 128) ? &Ks[row][quad*4] : &Vs[row][quad*4];
            *(float4*)dst = vv;
        }
        __syncthreads();

        float s[32];
        float tmax = -1e30f;
        #pragma unroll
        for (int j = 0; j < 32; j++) {
            const float4* kr = (const float4*)&Ks[j][0];
            float4 k0 = kr[0], k1 = kr[1], k2 = kr[2], k3 = kr[3];
            float d = qv[0]*k0.x + qv[1]*k0.y + qv[2]*k0.z + qv[3]*k0.w
                    + qv[4]*k1.x + qv[5]*k1.y + qv[6]*k1.z + qv[7]*k1.w
                    + qv[8]*k2.x + qv[9]*k2.y + qv[10]*k2.z + qv[11]*k2.w
                    + qv[12]*k3.x + qv[13]*k3.y + qv[14]*k3.z + qv[15]*k3.w;
            d *= 0.25f;
            s[j] = ((kb + j) <= q) ? d : -1e30f;
            tmax = fmaxf(tmax, s[j]);
        }
        if (tmax > -1e29f) {
            float mnew  = fmaxf(mrun, tmax);
            float alpha = __expf(mrun - mnew);
            lsum *= alpha;
            #pragma unroll
            for (int i = 0; i < 16; i++) acc[i] *= alpha;
            #pragma unroll
            for (int j = 0; j < 32; j++) {
                float p = (s[j] > -1e29f) ? __expf(s[j] - mnew) : 0.f;
                lsum += p;
                const float4* vr = (const float4*)&Vs[j][0];
                float4 v0 = vr[0], v1 = vr[1], v2 = vr[2], v3 = vr[3];
                acc[0]  += p*v0.x; acc[1]  += p*v0.y; acc[2]  += p*v0.z; acc[3]  += p*v0.w;
                acc[4]  += p*v1.x; acc[5]  += p*v1.y; acc[6]  += p*v1.z; acc[7]  += p*v1.w;
                acc[8]  += p*v2.x; acc[9]  += p*v2.y; acc[10] += p*v2.z; acc[11] += p*v2.w;
                acc[12] += p*v3.x; acc[13] += p*v3.y; acc[14] += p*v3.z; acc[15] += p*v3.w;
            }
            mrun = mnew;
        }
    }

    float inv = 1.f / lsum;
    float* orow = g_att + ((size_t)(b*Mm + q))*Dd + h*HDIM;
    #pragma unroll
    for (int t4 = 0; t4 < 4; t4++) {
        float4 o;
        o.x = acc[t4*4+0]*inv; o.y = acc[t4*4+1]*inv;
        o.z = acc[t4*4+2]*inv; o.w = acc[t4*4+3]*inv;
        *(float4*)(orow + t4*4) = o;
    }
}

// ----------------------------- loss ------------------------------------------
__global__ void __launch_bounds__(256) k_loss(const int* __restrict__ tgt,
                                              const float* __restrict__ logits) {
    int tok = blockIdx.x * 256 + threadIdx.x;
    const float* lp = logits + (size_t)tok * Vv;
    float vals[32];
    float mx = -1e30f;
    #pragma unroll
    for (int e = 0; e < 8; e++) {
        float4 v = *(const float4*)(lp + e*4);
        vals[e*4+0] = v.x; vals[e*4+1] = v.y; vals[e*4+2] = v.z; vals[e*4+3] = v.w;
        mx = fmaxf(mx, fmaxf(fmaxf(v.x, v.y), fmaxf(v.z, v.w)));
    }
    float se = 0.f;
    #pragma unroll
    for (int j = 0; j < 32; j++) se += expf(vals[j] - mx);
    float tv = lp[tgt[tok]];
    float nll = -(tv - mx - logf(se));

    __shared__ float red[256];
    red[threadIdx.x] = nll; __syncthreads();
    for (int s = 128; s > 0; s >>= 1) {
        if (threadIdx.x < s) red[threadIdx.x] += red[threadIdx.x + s];
        __syncthreads();
    }
    if (threadIdx.x == 0) g_losspart[blockIdx.x] = red[0];
}

__global__ void k_loss2(float* out) {
    __shared__ float red[64];
    red[threadIdx.x] = g_losspart[threadIdx.x]; __syncthreads();
    for (int s = 32; s > 0; s >>= 1) {
        if (threadIdx.x < s) red[threadIdx.x] += red[threadIdx.x + s];
        __syncthreads();
    }
    if (threadIdx.x == 0) out[0] = red[0] / (float)TOK;
}

// ----------------------------- host driver -----------------------------------
extern "C" void kernel_launch(void* const* d_in, const int* in_sizes, int n_in,
                              void* d_out, int out_size) {
    const int*   idx = (const int*)  d_in[0];
    const int*   tgt = (const int*)  d_in[1];
    const float* emb = (const float*)d_in[2];
    const float* rms = (const float*)d_in[3];
    const float* Wq  = (const float*)d_in[4];
    const float* Wk  = (const float*)d_in[5];
    const float* Wv  = (const float*)d_in[6];
    const float* inw = (const float*)d_in[7];
    const float* inb = (const float*)d_in[8];
    const float* opw = (const float*)d_in[9];
    const float* opb = (const float*)d_in[10];
    const float* lw  = (const float*)d_in[11];
    const float* lb  = (const float*)d_in[12];
    const float* ow  = (const float*)d_in[13];
    const float* ob  = (const float*)d_in[14];
    float* out = (float*)d_out;

    float *x0, *q, *k, *v, *qp, *kp, *vp, *att, *x1, *x2, *x3;
    cudaGetSymbolAddress((void**)&x0,  g_x0);
    cudaGetSymbolAddress((void**)&q,   g_q);
    cudaGetSymbolAddress((void**)&k,   g_k);
    cudaGetSymbolAddress((void**)&v,   g_v);
    cudaGetSymbolAddress((void**)&qp,  g_qp);
    cudaGetSymbolAddress((void**)&kp,  g_kp);
    cudaGetSymbolAddress((void**)&vp,  g_vp);
    cudaGetSymbolAddress((void**)&att, g_att);
    cudaGetSymbolAddress((void**)&x1,  g_x1);
    cudaGetSymbolAddress((void**)&x2,  g_x2);
    cudaGetSymbolAddress((void**)&x3,  g_x3);

    const int SM64 = (128 + 64) * PITCH * 4;   // 101376 bytes
    const int SM32 = (128 + 32) * PITCH * 4;   //  84480 bytes
    cudaFuncSetAttribute(k_mma_gemm<64>, cudaFuncAttributeMaxDynamicSharedMemorySize, SM64);
    cudaFuncSetAttribute(k_mma_gemm<32>, cudaFuncAttributeMaxDynamicSharedMemorySize, SM32);

    k_rope_tables<<<Mm, 64>>>();
    k_embed<<<dim3(Bb, 128), 256>>>(idx, emb);
    k_inv<<<Bb, 128>>>();
    k_norm<<<TOK*Dd/256, 256>>>(x0, rms, x0);

    // QKV projections with fused RoPE (flags=2)
    k_mma_gemm<64><<<dim3(128, 2), 256, SM64>>>(x0, Wq, nullptr, nullptr, q, 128, 2);
    k_mma_gemm<64><<<dim3(128, 2), 256, SM64>>>(x0, Wk, nullptr, nullptr, k, 128, 2);
    k_mma_gemm<64><<<dim3(128, 2), 256, SM64>>>(x0, Wv, nullptr, nullptr, v, 128, 2);

    // in_proj
    k_mma_gemm<64><<<dim3(128, 2), 256, SM64>>>(q, inw,            inb,        nullptr, qp, 128, 0);
    k_mma_gemm<64><<<dim3(128, 2), 256, SM64>>>(k, inw + Dd*Dd,    inb + Dd,   nullptr, kp, 128, 0);
    k_mma_gemm<64><<<dim3(128, 2), 256, SM64>>>(v, inw + 2*Dd*Dd,  inb + 2*Dd, nullptr, vp, 128, 0);

    k_attn<<<dim3(8, 64), 256>>>();

    // out_proj + residual
    k_mma_gemm<64><<<dim3(128, 2), 256, SM64>>>(att, opw, opb, x0, x1, 128, 0);

    k_ssq<<<dim3(Bb, 128), 256>>>(x1);
    k_inv<<<Bb, 128>>>();
    k_norm<<<TOK*Dd/256, 256>>>(x1, rms, x2);

    // MLP: relu + residual (flags=1)
    k_mma_gemm<64><<<dim3(128, 2), 256, SM64>>>(x2, lw, lb, x2, x3, 128, 1);

    // logits
    k_mma_gemm<32><<<dim3(128, 1), 256, SM32>>>(x3, ow, ob, nullptr, out, Vv, 0);

    k_loss<<<TOK/256, 256>>>(tgt, out);
    if (out_size > TOK*Vv) k_loss2<<<1, 64>>>(out + (size_t)TOK*Vv);
}

// round 4
// speedup vs baseline: 2.2332x; 2.0696x over previous
#include <cuda_runtime.h>
#include <cuda_bf16.h>
#include <math.h>
#include <stdint.h>

#define Bb 8
#define Mm 2048
#define Dd 128
#define HDIM 16
#define Vv 32
#define TOK (Bb*Mm)          // 16384
#define SLAB (Mm*Dd)         // 262144 elements per batch slab

// ----------------------------- scratch (static device globals) ---------------
__device__ float g_x0[TOK*Dd];
__device__ float g_q [TOK*Dd];
__device__ float g_k [TOK*Dd];
__device__ float g_v [TOK*Dd];
__device__ float g_att[TOK*Dd];
__device__ float g_x1[TOK*Dd];
__device__ float g_x2[TOK*Dd];
__device__ float g_x3[TOK*Dd];
// packed bf16x2 (lo half = even col) hi/lo split of projected q/k/v
__device__ uint32_t g_qh[TOK*64];
__device__ uint32_t g_ql[TOK*64];
__device__ uint32_t g_kh[TOK*64];
__device__ uint32_t g_kl[TOK*64];
__device__ uint32_t g_vh[TOK*64];
__device__ uint32_t g_vl[TOK*64];
__device__ float g_cos[Mm*64];
__device__ float g_sin[Mm*64];
__device__ float g_part[Bb*128];
__device__ float g_inv[Bb];
__device__ float g_losspart[64];

// ----------------------------- helpers ----------------------------------------
__device__ __forceinline__ float f2tf32(float v) {
    float r; asm("cvt.rna.tf32.f32 %0, %1;" : "=f"(r) : "f"(v)); return r;
}
__device__ __forceinline__ void mma_tf32(float c[4], const uint32_t a[4],
                                         const uint32_t b[2]) {
    asm volatile(
        "mma.sync.aligned.m16n8k8.row.col.f32.tf32.tf32.f32 "
        "{%0,%1,%2,%3}, {%4,%5,%6,%7}, {%8,%9}, {%0,%1,%2,%3};"
        : "+f"(c[0]), "+f"(c[1]), "+f"(c[2]), "+f"(c[3])
        : "r"(a[0]), "r"(a[1]), "r"(a[2]), "r"(a[3]), "r"(b[0]), "r"(b[1]));
}
__device__ __forceinline__ void mma_bf16(float c[4], const uint32_t a[4],
                                         uint32_t b0, uint32_t b1) {
    asm volatile(
        "mma.sync.aligned.m16n8k16.row.col.f32.bf16.bf16.f32 "
        "{%0,%1,%2,%3}, {%4,%5,%6,%7}, {%8,%9}, {%0,%1,%2,%3};"
        : "+f"(c[0]), "+f"(c[1]), "+f"(c[2]), "+f"(c[3])
        : "r"(a[0]), "r"(a[1]), "r"(a[2]), "r"(a[3]), "r"(b0), "r"(b1));
}
__device__ __forceinline__ void split(float v, uint32_t& hi, uint32_t& lo) {
    float h = f2tf32(v);
    float l = f2tf32(v - h);
    hi = __float_as_uint(h);
    lo = __float_as_uint(l);
}
// pack two floats into bf16x2 hi/lo pair (lo halfword = x)
__device__ __forceinline__ void bf16_split2(float x, float y,
                                            uint32_t& hi, uint32_t& lo) {
    __nv_bfloat162 hb = __float22bfloat162_rn(make_float2(x, y));
    float2 back = __bfloat1622float2(hb);
    __nv_bfloat162 lb = __float22bfloat162_rn(make_float2(x - back.x, y - back.y));
    hi = *(uint32_t*)&hb;
    lo = *(uint32_t*)&lb;
}

// ----------------------------- tensor-core tf32 GEMM --------------------------
// C[16384 x Ncols] = A[16384 x 128] @ W[Ncols x 128]^T (+bias)(relu)(rope)(+resid)
// If Ohi != null: write packed bf16 hi/lo pairs instead of (or besides) fp32 C.
// flags: bit0 = relu, bit1 = rope
#define PITCH 132
template <int NT>
__global__ void __launch_bounds__(256, 2) k_mma_gemm(
    const float* __restrict__ A, const float* __restrict__ W,
    const float* __restrict__ bias, const float* __restrict__ resid,
    float* __restrict__ C, uint32_t* __restrict__ Ohi, uint32_t* __restrict__ Olo,
    int ldc, int flags)
{
    extern __shared__ float sm[];
    float* As = sm;                    // [128][PITCH]
    float* Ws = sm + 128 * PITCH;      // [NT][PITCH]
    constexpr int TN = NT / 16;

    int tid = threadIdx.x;
    int rowBase = blockIdx.x * 128;
    int colBase = blockIdx.y * NT;

    #pragma unroll
    for (int i = 0; i < 16; i++) {
        int f = tid + i * 256;
        int row = f >> 5, q = f & 31;
        float4 v = *(const float4*)(A + (size_t)(rowBase + row) * 128 + q * 4);
        *(float4*)(As + row * PITCH + q * 4) = v;
    }
    #pragma unroll
    for (int i = 0; i < NT / 8; i++) {
        int f = tid + i * 256;
        int row = f >> 5, q = f & 31;
        float4 v = *(const float4*)(W + (size_t)(colBase + row) * 128 + q * 4);
        *(float4*)(Ws + row * PITCH + q * 4) = v;
    }
    __syncthreads();

    int w = tid >> 5, lane = tid & 31;
    int g = lane >> 2, tg = lane & 3;
    int mBase = (w & 3) * 32;
    int nBase = (w >> 2) * (NT / 2);

    float acc[2][TN][4];
    #pragma unroll
    for (int tm = 0; tm < 2; tm++)
        #pragma unroll
        for (int tn = 0; tn < TN; tn++)
            #pragma unroll
            for (int e = 0; e < 4; e++) acc[tm][tn][e] = 0.f;

    #pragma unroll 4
    for (int ks = 0; ks < 16; ks++) {
        int k0 = ks * 8;
        uint32_t ahi[2][4], alo[2][4];
        #pragma unroll
        for (int tm = 0; tm < 2; tm++) {
            const float* p  = As + (mBase + tm * 16 + g) * PITCH + k0 + tg;
            const float* p8 = p + 8 * PITCH;
            split(p [0], ahi[tm][0], alo[tm][0]);
            split(p8[0], ahi[tm][1], alo[tm][1]);
            split(p [4], ahi[tm][2], alo[tm][2]);
            split(p8[4], ahi[tm][3], alo[tm][3]);
        }
        uint32_t bhi[TN][2], blo[TN][2];
        #pragma unroll
        for (int tn = 0; tn < TN; tn++) {
            const float* p = Ws + (nBase + tn * 8 + g) * PITCH + k0 + tg;
            split(p[0], bhi[tn][0], blo[tn][0]);
            split(p[4], bhi[tn][1], blo[tn][1]);
        }
        #pragma unroll
        for (int tm = 0; tm < 2; tm++)
            #pragma unroll
            for (int tn = 0; tn < TN; tn++) {
                mma_tf32(acc[tm][tn], ahi[tm], bhi[tn]);
                mma_tf32(acc[tm][tn], alo[tm], bhi[tn]);
                mma_tf32(acc[tm][tn], ahi[tm], blo[tn]);
            }
    }

    #pragma unroll
    for (int tm = 0; tm < 2; tm++) {
        #pragma unroll
        for (int tn = 0; tn < TN; tn++) {
            int col = colBase + nBase + tn * 8 + tg * 2;
            #pragma unroll
            for (int half = 0; half < 2; half++) {
                int row = rowBase + mBase + tm * 16 + g + half * 8;
                float v0 = acc[tm][tn][half * 2 + 0];
                float v1 = acc[tm][tn][half * 2 + 1];
                if (bias) { v0 += bias[col]; v1 += bias[col + 1]; }
                if (flags & 1) { v0 = fmaxf(v0, 0.f); v1 = fmaxf(v1, 0.f); }
                if (flags & 2) {
                    int m = row & (Mm - 1);
                    int i = col >> 1;
                    float cc = g_cos[m * 64 + i];
                    float ss = g_sin[m * 64 + i];
                    float te = v0, to = v1;
                    v0 =  te * cc + to * ss;
                    v1 = -te * ss + to * cc;
                }
                if (resid) {
                    v0 += resid[(size_t)row * ldc + col];
                    v1 += resid[(size_t)row * ldc + col + 1];
                }
                if (Ohi) {
                    uint32_t hi, lo;
                    bf16_split2(v0, v1, hi, lo);
                    Ohi[(size_t)row * 64 + (col >> 1)] = hi;
                    Olo[(size_t)row * 64 + (col >> 1)] = lo;
                } else {
                    float2 o; o.x = v0; o.y = v1;
                    *(float2*)(C + (size_t)row * ldc + col) = o;
                }
            }
        }
    }
}

// ----------------------------- mma.sync bf16 flash attention -----------------
// grid 1024 blocks: heavy qt first. Block = (bh, 128 q-rows). k-tiles of 64.
__global__ void __launch_bounds__(256, 2) k_attn_mma() {
    int bid = blockIdx.x;
    int qt = 15 - (bid >> 6);        // heavy-first
    int bh = bid & 63;
    int b = bh >> 3, h = bh & 7;
    int tid = threadIdx.x;
    int w = tid >> 5, lane = tid & 31;
    int g = lane >> 2, tg = lane & 3;
    int tokbase = b * Mm;
    int qBase = qt * 128 + w * 16;   // warp's first q row (within seq)

    __shared__ uint32_t Khi[64*9], Klo[64*9];      // [key][8 bf16x2 + pad]
    __shared__ uint32_t Vthi[16*36], Vtlo[16*36];  // [d][64 keys bf16, pitch 36 words]

    // Q fragments (A layout, m16n8k16): rows g/g+8, d-pairs tg / tg+4
    uint32_t qh[4], ql[4];
    {
        const uint32_t* ph = g_qh + (size_t)(tokbase + qBase) * 64 + h * 8;
        const uint32_t* pl = g_ql + (size_t)(tokbase + qBase) * 64 + h * 8;
        qh[0] = ph[(size_t)g * 64 + tg];
        qh[1] = ph[(size_t)(g + 8) * 64 + tg];
        qh[2] = ph[(size_t)g * 64 + tg + 4];
        qh[3] = ph[(size_t)(g + 8) * 64 + tg + 4];
        ql[0] = pl[(size_t)g * 64 + tg];
        ql[1] = pl[(size_t)(g + 8) * 64 + tg];
        ql[2] = pl[(size_t)g * 64 + tg + 4];
        ql[3] = pl[(size_t)(g + 8) * 64 + tg + 4];
    }

    float o[2][4];
    #pragma unroll
    for (int t = 0; t < 2; t++)
        #pragma unroll
        for (int e = 0; e < 4; e++) o[t][e] = 0.f;
    float m0 = -1e30f, m1 = -1e30f, l0 = 0.f, l1 = 0.f;

    int q0 = qBase + g;          // row for c0/c1
    int q1 = qBase + g + 8;      // row for c2/c3

    int nkt = 2 * qt + 2;        // 64-key tiles
    for (int kt = 0; kt < nkt; kt++) {
        int kb = kt * 64;
        __syncthreads();
        #pragma unroll
        for (int i = 0; i < 2; i++) {
            int wv = tid + i * 256;          // 0..511
            int key = wv >> 3, c = wv & 7;
            size_t ga = (size_t)(tokbase + kb + key) * 64 + h * 8 + c;
            Khi[key * 9 + c] = g_kh[ga];
            Klo[key * 9 + c] = g_kl[ga];
            uint32_t pv = g_vh[ga];
            uint32_t pl = g_vl[ga];
            ((uint16_t*)Vthi)[(2*c    ) * 72 + key] = (uint16_t)(pv & 0xFFFF);
            ((uint16_t*)Vthi)[(2*c + 1) * 72 + key] = (uint16_t)(pv >> 16);
            ((uint16_t*)Vtlo)[(2*c    ) * 72 + key] = (uint16_t)(pl & 0xFFFF);
            ((uint16_t*)Vtlo)[(2*c + 1) * 72 + key] = (uint16_t)(pl >> 16);
        }
        __syncthreads();

        // ---- S = Q K^T (8 n-tiles of 8 keys), 3-term bf16
        float s[8][4];
        #pragma unroll
        for (int nt = 0; nt < 8; nt++) {
            uint32_t bh0 = Khi[(nt * 8 + g) * 9 + tg];
            uint32_t bh1 = Khi[(nt * 8 + g) * 9 + tg + 4];
            uint32_t bl0 = Klo[(nt * 8 + g) * 9 + tg];
            uint32_t bl1 = Klo[(nt * 8 + g) * 9 + tg + 4];
            #pragma unroll
            for (int e = 0; e < 4; e++) s[nt][e] = 0.f;
            mma_bf16(s[nt], qh, bh0, bh1);
            mma_bf16(s[nt], ql, bh0, bh1);
            mma_bf16(s[nt], qh, bl0, bl1);
        }

        // ---- mask + scale + row max
        float tmax0 = -1e30f, tmax1 = -1e30f;
        #pragma unroll
        for (int nt = 0; nt < 8; nt++) {
            int kc = kb + nt * 8 + 2 * tg;
            s[nt][0] = (kc     <= q0) ? s[nt][0] * 0.25f : -1e30f;
            s[nt][1] = (kc + 1 <= q0) ? s[nt][1] * 0.25f : -1e30f;
            s[nt][2] = (kc     <= q1) ? s[nt][2] * 0.25f : -1e30f;
            s[nt][3] = (kc + 1 <= q1) ? s[nt][3] * 0.25f : -1e30f;
            tmax0 = fmaxf(tmax0, fmaxf(s[nt][0], s[nt][1]));
            tmax1 = fmaxf(tmax1, fmaxf(s[nt][2], s[nt][3]));
        }
        tmax0 = fmaxf(tmax0, __shfl_xor_sync(0xffffffffu, tmax0, 1));
        tmax0 = fmaxf(tmax0, __shfl_xor_sync(0xffffffffu, tmax0, 2));
        tmax1 = fmaxf(tmax1, __shfl_xor_sync(0xffffffffu, tmax1, 1));
        tmax1 = fmaxf(tmax1, __shfl_xor_sync(0xffffffffu, tmax1, 2));

        float mn0 = fmaxf(m0, tmax0), mn1 = fmaxf(m1, tmax1);
        float a0 = __expf(m0 - mn0), a1 = __expf(m1 - mn1);
        m0 = mn0; m1 = mn1;
        l0 *= a0; l1 *= a1;
        #pragma unroll
        for (int t = 0; t < 2; t++) {
            o[t][0] *= a0; o[t][1] *= a0; o[t][2] *= a1; o[t][3] *= a1;
        }

        // ---- P = exp(S - m), split to bf16 hi/lo (C frag == A frag identity)
        uint32_t phi[8][2], plo[8][2];
        #pragma unroll
        for (int nt = 0; nt < 8; nt++) {
            float p0 = __expf(s[nt][0] - mn0);
            float p1 = __expf(s[nt][1] - mn0);
            float p2 = __expf(s[nt][2] - mn1);
            float p3 = __expf(s[nt][3] - mn1);
            l0 += p0 + p1; l1 += p2 + p3;
            bf16_split2(p0, p1, phi[nt][0], plo[nt][0]);
            bf16_split2(p2, p3, phi[nt][1], plo[nt][1]);
        }

        // ---- O += P V (4 k-groups of 16 keys, 2 d-tiles)
        #pragma unroll
        for (int kg = 0; kg < 4; kg++) {
            uint32_t ah[4] = { phi[2*kg][0], phi[2*kg][1], phi[2*kg+1][0], phi[2*kg+1][1] };
            uint32_t al[4] = { plo[2*kg][0], plo[2*kg][1], plo[2*kg+1][0], plo[2*kg+1][1] };
            #pragma unroll
            for (int t = 0; t < 2; t++) {
                int n = t * 8 + g;
                uint32_t bh0 = Vthi[n * 36 + kg * 8 + tg];
                uint32_t bh1 = Vthi[n * 36 + kg * 8 + tg + 4];
                uint32_t bl0 = Vtlo[n * 36 + kg * 8 + tg];
                uint32_t bl1 = Vtlo[n * 36 + kg * 8 + tg + 4];
                mma_bf16(o[t], ah, bh0, bh1);
                mma_bf16(o[t], al, bh0, bh1);
                mma_bf16(o[t], ah, bl0, bl1);
            }
        }
    }

    l0 += __shfl_xor_sync(0xffffffffu, l0, 1);
    l0 += __shfl_xor_sync(0xffffffffu, l0, 2);
    l1 += __shfl_xor_sync(0xffffffffu, l1, 1);
    l1 += __shfl_xor_sync(0xffffffffu, l1, 2);
    float i0 = 1.f / l0, i1 = 1.f / l1;

    #pragma unroll
    for (int t = 0; t < 2; t++) {
        int d = h * HDIM + t * 8 + 2 * tg;
        float2 r0; r0.x = o[t][0] * i0; r0.y = o[t][1] * i0;
        float2 r1; r1.x = o[t][2] * i1; r1.y = o[t][3] * i1;
        *(float2*)(g_att + (size_t)(tokbase + q0) * 128 + d) = r0;
        *(float2*)(g_att + (size_t)(tokbase + q1) * 128 + d) = r1;
    }
}

// ----------------------------- RoPE tables -----------------------------------
__global__ void k_rope_tables() {
    int i   = threadIdx.x;
    int pos = blockIdx.x;
    float base = powf(10000.0f, -2.0f * ((float)i - 1.0f) / 128.0f);
    float ang  = (float)pos * base;
    float s, c;
    sincosf(ang, &s, &c);
    g_cos[pos*64 + i] = c;
    g_sin[pos*64 + i] = s;
}

// ----------------------------- embedding gather + ssq partials ---------------
__global__ void __launch_bounds__(256) k_embed(const int* __restrict__ idx,
                                               const float* __restrict__ emb) {
    int b   = blockIdx.x;
    int seg = blockIdx.y;
    int tid = threadIdx.x;
    int tok0 = seg * 16;
    float ss = 0.f;
    #pragma unroll
    for (int e = 0; e < 8; e++) {
        int li = tid + e * 256;
        int t  = tok0 + (li >> 7);
        int d  = li & 127;
        int row = idx[b*Mm + t];
        float vv = emb[row*Dd + d];
        g_x0[((size_t)(b*Mm + t))*Dd + d] = vv;
        ss += vv * vv;
    }
    __shared__ float red[256];
    red[tid] = ss; __syncthreads();
    for (int s = 128; s > 0; s >>= 1) {
        if (tid < s) red[tid] += red[tid + s];
        __syncthreads();
    }
    if (tid == 0) g_part[b*128 + seg] = red[0];
}

__global__ void __launch_bounds__(256) k_ssq(const float* __restrict__ x) {
    int b   = blockIdx.x;
    int seg = blockIdx.y;
    int tid = threadIdx.x;
    const float* p = x + (size_t)b*SLAB + seg*2048;
    float ss = 0.f;
    #pragma unroll
    for (int e = 0; e < 8; e++) {
        float vv = p[tid + e*256];
        ss += vv * vv;
    }
    __shared__ float red[256];
    red[tid] = ss; __syncthreads();
    for (int s = 128; s > 0; s >>= 1) {
        if (tid < s) red[tid] += red[tid + s];
        __syncthreads();
    }
    if (tid == 0) g_part[b*128 + seg] = red[0];
}

__global__ void k_inv() {
    int b = blockIdx.x;
    int tid = threadIdx.x;
    __shared__ float red[128];
    red[tid] = g_part[b*128 + tid]; __syncthreads();
    for (int s = 64; s > 0; s >>= 1) {
        if (tid < s) red[tid] += red[tid + s];
        __syncthreads();
    }
    if (tid == 0) g_inv[b] = 512.0f / sqrtf(red[0]);
}

__global__ void __launch_bounds__(256) k_norm(const float* __restrict__ x,
                                              const float* __restrict__ scale,
                                              float* __restrict__ y) {
    int i = blockIdx.x * 256 + threadIdx.x;
    int b = i >> 18;
    int r = i & (SLAB - 1);
    int m = r >> 7;
    int d = r & 127;
    y[i] = x[i] * g_inv[b] * scale[m*Dd + d];
}

// ----------------------------- loss ------------------------------------------
__global__ void __launch_bounds__(256) k_loss(const int* __restrict__ tgt,
                                              const float* __restrict__ logits) {
    int tok = blockIdx.x * 256 + threadIdx.x;
    const float* lp = logits + (size_t)tok * Vv;
    float vals[32];
    float mx = -1e30f;
    #pragma unroll
    for (int e = 0; e < 8; e++) {
        float4 v = *(const float4*)(lp + e*4);
        vals[e*4+0] = v.x; vals[e*4+1] = v.y; vals[e*4+2] = v.z; vals[e*4+3] = v.w;
        mx = fmaxf(mx, fmaxf(fmaxf(v.x, v.y), fmaxf(v.z, v.w)));
    }
    float se = 0.f;
    #pragma unroll
    for (int j = 0; j < 32; j++) se += expf(vals[j] - mx);
    float tv = lp[tgt[tok]];
    float nll = -(tv - mx - logf(se));

    __shared__ float red[256];
    red[threadIdx.x] = nll; __syncthreads();
    for (int s = 128; s > 0; s >>= 1) {
        if (threadIdx.x < s) red[threadIdx.x] += red[threadIdx.x + s];
        __syncthreads();
    }
    if (threadIdx.x == 0) g_losspart[blockIdx.x] = red[0];
}

__global__ void k_loss2(float* out) {
    __shared__ float red[64];
    red[threadIdx.x] = g_losspart[threadIdx.x]; __syncthreads();
    for (int s = 32; s > 0; s >>= 1) {
        if (threadIdx.x < s) red[threadIdx.x] += red[threadIdx.x + s];
        __syncthreads();
    }
    if (threadIdx.x == 0) out[0] = red[0] / (float)TOK;
}

// ----------------------------- host driver -----------------------------------
extern "C" void kernel_launch(void* const* d_in, const int* in_sizes, int n_in,
                              void* d_out, int out_size) {
    const int*   idx = (const int*)  d_in[0];
    const int*   tgt = (const int*)  d_in[1];
    const float* emb = (const float*)d_in[2];
    const float* rms = (const float*)d_in[3];
    const float* Wq  = (const float*)d_in[4];
    const float* Wk  = (const float*)d_in[5];
    const float* Wv  = (const float*)d_in[6];
    const float* inw = (const float*)d_in[7];
    const float* inb = (const float*)d_in[8];
    const float* opw = (const float*)d_in[9];
    const float* opb = (const float*)d_in[10];
    const float* lw  = (const float*)d_in[11];
    const float* lb  = (const float*)d_in[12];
    const float* ow  = (const float*)d_in[13];
    const float* ob  = (const float*)d_in[14];
    float* out = (float*)d_out;

    float *x0, *q, *k, *v, *att, *x1, *x2, *x3;
    uint32_t *qh, *ql, *kh, *kl, *vh, *vl;
    cudaGetSymbolAddress((void**)&x0,  g_x0);
    cudaGetSymbolAddress((void**)&q,   g_q);
    cudaGetSymbolAddress((void**)&k,   g_k);
    cudaGetSymbolAddress((void**)&v,   g_v);
    cudaGetSymbolAddress((void**)&att, g_att);
    cudaGetSymbolAddress((void**)&x1,  g_x1);
    cudaGetSymbolAddress((void**)&x2,  g_x2);
    cudaGetSymbolAddress((void**)&x3,  g_x3);
    cudaGetSymbolAddress((void**)&qh,  g_qh);
    cudaGetSymbolAddress((void**)&ql,  g_ql);
    cudaGetSymbolAddress((void**)&kh,  g_kh);
    cudaGetSymbolAddress((void**)&kl,  g_kl);
    cudaGetSymbolAddress((void**)&vh,  g_vh);
    cudaGetSymbolAddress((void**)&vl,  g_vl);

    const int SM64 = (128 + 64) * PITCH * 4;
    const int SM32 = (128 + 32) * PITCH * 4;
    cudaFuncSetAttribute(k_mma_gemm<64>, cudaFuncAttributeMaxDynamicSharedMemorySize, SM64);
    cudaFuncSetAttribute(k_mma_gemm<32>, cudaFuncAttributeMaxDynamicSharedMemorySize, SM32);

    k_rope_tables<<<Mm, 64>>>();
    k_embed<<<dim3(Bb, 128), 256>>>(idx, emb);
    k_inv<<<Bb, 128>>>();
    k_norm<<<TOK*Dd/256, 256>>>(x0, rms, x0);

    // QKV projections with fused RoPE (flags=2), fp32 out
    k_mma_gemm<64><<<dim3(128, 2), 256, SM64>>>(x0, Wq, nullptr, nullptr, q, nullptr, nullptr, 128, 2);
    k_mma_gemm<64><<<dim3(128, 2), 256, SM64>>>(x0, Wk, nullptr, nullptr, k, nullptr, nullptr, 128, 2);
    k_mma_gemm<64><<<dim3(128, 2), 256, SM64>>>(x0, Wv, nullptr, nullptr, v, nullptr, nullptr, 128, 2);

    // in_proj -> packed bf16 hi/lo for attention
    k_mma_gemm<64><<<dim3(128, 2), 256, SM64>>>(q, inw,           inb,        nullptr, nullptr, qh, ql, 128, 0);
    k_mma_gemm<64><<<dim3(128, 2), 256, SM64>>>(k, inw + Dd*Dd,   inb + Dd,   nullptr, nullptr, kh, kl, 128, 0);
    k_mma_gemm<64><<<dim3(128, 2), 256, SM64>>>(v, inw + 2*Dd*Dd, inb + 2*Dd, nullptr, nullptr, vh, vl, 128, 0);

    k_attn_mma<<<1024, 256>>>();

    // out_proj + residual
    k_mma_gemm<64><<<dim3(128, 2), 256, SM64>>>(att, opw, opb, x0, x1, nullptr, nullptr, 128, 0);

    k_ssq<<<dim3(Bb, 128), 256>>>(x1);
    k_inv<<<Bb, 128>>>();
    k_norm<<<TOK*Dd/256, 256>>>(x1, rms, x2);

    // MLP: relu + residual
    k_mma_gemm<64><<<dim3(128, 2), 256, SM64>>>(x2, lw, lb, x2, x3, nullptr, nullptr, 128, 1);

    // logits
    k_mma_gemm<32><<<dim3(128, 1), 256, SM32>>>(x3, ow, ob, nullptr, out, nullptr, nullptr, Vv, 0);

    k_loss<<<TOK/256, 256>>>(tgt, out);
    if (out_size > TOK*Vv) k_loss2<<<1, 64>>>(out + (size_t)TOK*Vv);
}

// round 5
// speedup vs baseline: 3.1184x; 1.3964x over previous
#include <cuda_runtime.h>
#include <cuda_bf16.h>
#include <math.h>
#include <stdint.h>

#define Bb 8
#define Mm 2048
#define Dd 128
#define HDIM 16
#define Vv 32
#define TOK (Bb*Mm)          // 16384
#define SLAB (Mm*Dd)
#define P 68                 // smem word pitch: (4g+tg) mod 32 unique -> conflict-free frags

// ----------------------------- scratch ---------------------------------------
__device__ float g_x0[TOK*Dd];
__device__ float g_att[TOK*Dd];
__device__ float g_x1[TOK*Dd];
__device__ uint32_t g_qh[TOK*64];
__device__ uint32_t g_ql[TOK*64];
__device__ uint32_t g_kh[TOK*64];
__device__ uint32_t g_kl[TOK*64];
__device__ uint32_t g_vh[TOK*64];
__device__ uint32_t g_vl[TOK*64];
__device__ float g_cos[Mm*64];
__device__ float g_sin[Mm*64];
__device__ float g_part[Bb*128];
__device__ float g_part2[128];
__device__ float g_inv[Bb];
__device__ float g_inv2[Bb];
__device__ float g_losspart[128];

// ----------------------------- helpers ----------------------------------------
__device__ __forceinline__ void mma_bf16(float c[4], const uint32_t a[4],
                                         uint32_t b0, uint32_t b1) {
    asm volatile(
        "mma.sync.aligned.m16n8k16.row.col.f32.bf16.bf16.f32 "
        "{%0,%1,%2,%3}, {%4,%5,%6,%7}, {%8,%9}, {%0,%1,%2,%3};"
        : "+f"(c[0]), "+f"(c[1]), "+f"(c[2]), "+f"(c[3])
        : "r"(a[0]), "r"(a[1]), "r"(a[2]), "r"(a[3]), "r"(b0), "r"(b1));
}
__device__ __forceinline__ void bf16_split2(float x, float y,
                                            uint32_t& hi, uint32_t& lo) {
    __nv_bfloat162 hb = __float22bfloat162_rn(make_float2(x, y));
    float2 back = __bfloat1622float2(hb);
    __nv_bfloat162 lb = __float22bfloat162_rn(make_float2(x - back.x, y - back.y));
    hi = *(uint32_t*)&hb;
    lo = *(uint32_t*)&lb;
}
__device__ __forceinline__ float2 bf2_unpack(uint32_t w) {
    __nv_bfloat162 t;
    *(uint32_t*)&t = w;
    return __bfloat1622float2(t);
}
// split float4 -> two packed bf16x2 hi words + two lo words and store to planes
__device__ __forceinline__ void stage4(uint32_t* H, uint32_t* L, int idx,
                                       float a, float b, float c, float d) {
    uint32_t h0, l0, h1, l1;
    bf16_split2(a, b, h0, l0);
    bf16_split2(c, d, h1, l1);
    H[idx] = h0; H[idx + 1] = h1;
    L[idx] = l0; L[idx + 1] = l1;
}

// =============================================================================
// Fused QKV: C1 = norm(x0) @ Wsel^T ; rope(C1) ; out = C1r @ inw_sel^T + b
// grid (128, 3), 256 threads, 1 CTA/SM (139.8 KB smem)
// =============================================================================
__global__ void __launch_bounds__(256, 1) k_qkv(
    const float* __restrict__ x0, const float* __restrict__ rms,
    const float* __restrict__ Wq, const float* __restrict__ Wk,
    const float* __restrict__ Wv,
    const float* __restrict__ inw, const float* __restrict__ inb,
    uint32_t* __restrict__ qh_, uint32_t* __restrict__ ql_,
    uint32_t* __restrict__ kh_, uint32_t* __restrict__ kl_,
    uint32_t* __restrict__ vh_, uint32_t* __restrict__ vl_)
{
    extern __shared__ uint32_t smw[];
    uint32_t* Ah = smw;
    uint32_t* Al = Ah + 128 * P;
    uint32_t* Wh = Al + 128 * P;
    uint32_t* Wl = Wh + 128 * P;
    float* bias_s = (float*)(Wl + 128 * P);

    int which = blockIdx.y;
    const float* W1 = (which == 0) ? Wq : ((which == 1) ? Wk : Wv);
    const float* W2 = inw + which * (Dd * Dd);
    uint32_t* Oh = (which == 0) ? qh_ : ((which == 1) ? kh_ : vh_);
    uint32_t* Ol = (which == 0) ? ql_ : ((which == 1) ? kl_ : vl_);

    int tid = threadIdx.x;
    int rowBase = blockIdx.x * 128;
    float inv = g_inv[rowBase >> 11];
    if (tid < 128) bias_s[tid] = inb[which * 128 + tid];

    // stage A = norm(x0) and W1 as packed bf16 hi/lo
    #pragma unroll
    for (int i = 0; i < 16; i++) {
        int f = tid + i * 256;
        int row = f >> 5, q4 = f & 31;
        int m = (rowBase + row) & (Mm - 1);
        float4 xv = *(const float4*)(x0 + (size_t)(rowBase + row) * 128 + q4 * 4);
        float4 sv = *(const float4*)(rms + (size_t)m * 128 + q4 * 4);
        stage4(Ah, Al, row * P + q4 * 2,
               xv.x * inv * sv.x, xv.y * inv * sv.y,
               xv.z * inv * sv.z, xv.w * inv * sv.w);
        float4 wv = *(const float4*)(W1 + (size_t)row * 128 + q4 * 4);
        stage4(Wh, Wl, row * P + q4 * 2, wv.x, wv.y, wv.z, wv.w);
    }
    __syncthreads();

    int w = tid >> 5, lane = tid & 31, g = lane >> 2, tg = lane & 3;
    int r0 = w * 16 + g, r1 = r0 + 8;

    // ---- GEMM1
    float acc[16][4];
    #pragma unroll
    for (int nt = 0; nt < 16; nt++)
        #pragma unroll
        for (int e = 0; e < 4; e++) acc[nt][e] = 0.f;

    #pragma unroll
    for (int kg = 0; kg < 8; kg++) {
        int b0 = kg * 8 + tg;
        uint32_t ah[4], al[4];
        ah[0] = Ah[r0 * P + b0];     ah[1] = Ah[r1 * P + b0];
        ah[2] = Ah[r0 * P + b0 + 4]; ah[3] = Ah[r1 * P + b0 + 4];
        al[0] = Al[r0 * P + b0];     al[1] = Al[r1 * P + b0];
        al[2] = Al[r0 * P + b0 + 4]; al[3] = Al[r1 * P + b0 + 4];
        #pragma unroll
        for (int nt = 0; nt < 16; nt++) {
            int n = nt * 8 + g;
            uint32_t bh0 = Wh[n * P + b0], bh1 = Wh[n * P + b0 + 4];
            uint32_t bl0 = Wl[n * P + b0], bl1 = Wl[n * P + b0 + 4];
            mma_bf16(acc[nt], ah, bh0, bh1);
            mma_bf16(acc[nt], al, bh0, bh1);
            mma_bf16(acc[nt], ah, bl0, bl1);
        }
    }

    // ---- RoPE in registers (cols 2tg,2tg+1 of each n-tile form a pair)
    int m0 = (rowBase + r0) & (Mm - 1), m1 = (rowBase + r1) & (Mm - 1);
    #pragma unroll
    for (int nt = 0; nt < 16; nt++) {
        int i = nt * 4 + tg;
        float c0 = g_cos[m0 * 64 + i], s0 = g_sin[m0 * 64 + i];
        float c1 = g_cos[m1 * 64 + i], s1 = g_sin[m1 * 64 + i];
        float te = acc[nt][0], to = acc[nt][1];
        acc[nt][0] =  te * c0 + to * s0;
        acc[nt][1] = -te * s0 + to * c0;
        te = acc[nt][2]; to = acc[nt][3];
        acc[nt][2] =  te * c1 + to * s1;
        acc[nt][3] = -te * s1 + to * c1;
    }

    // ---- repack C1 as GEMM2 A fragments (C frag == A frag identity)
    uint32_t a2h[8][4], a2l[8][4];
    #pragma unroll
    for (int kg = 0; kg < 8; kg++) {
        bf16_split2(acc[2*kg][0],   acc[2*kg][1],   a2h[kg][0], a2l[kg][0]);
        bf16_split2(acc[2*kg][2],   acc[2*kg][3],   a2h[kg][1], a2l[kg][1]);
        bf16_split2(acc[2*kg+1][0], acc[2*kg+1][1], a2h[kg][2], a2l[kg][2]);
        bf16_split2(acc[2*kg+1][2], acc[2*kg+1][3], a2h[kg][3], a2l[kg][3]);
    }
    __syncthreads();

    // ---- stage W2 into A region
    #pragma unroll
    for (int i = 0; i < 16; i++) {
        int f = tid + i * 256;
        int row = f >> 5, q4 = f & 31;
        float4 wv = *(const float4*)(W2 + (size_t)row * 128 + q4 * 4);
        stage4(Ah, Al, row * P + q4 * 2, wv.x, wv.y, wv.z, wv.w);
    }
    __syncthreads();

    // ---- GEMM2 + epilogue
    int grow0 = rowBase + r0, grow1 = rowBase + r1;
    #pragma unroll
    for (int nt = 0; nt < 16; nt++) {
        float a2[4] = {0.f, 0.f, 0.f, 0.f};
        #pragma unroll
        for (int kg = 0; kg < 8; kg++) {
            int b0 = kg * 8 + tg;
            int n = nt * 8 + g;
            uint32_t bh0 = Ah[n * P + b0], bh1 = Ah[n * P + b0 + 4];
            uint32_t bl0 = Al[n * P + b0], bl1 = Al[n * P + b0 + 4];
            mma_bf16(a2, a2h[kg], bh0, bh1);
            mma_bf16(a2, a2l[kg], bh0, bh1);
            mma_bf16(a2, a2h[kg], bl0, bl1);
        }
        int col = nt * 8 + 2 * tg;
        float v0 = a2[0] + bias_s[col], v1 = a2[1] + bias_s[col + 1];
        float v2 = a2[2] + bias_s[col], v3 = a2[3] + bias_s[col + 1];
        uint32_t h, l;
        bf16_split2(v0, v1, h, l);
        Oh[(size_t)grow0 * 64 + nt * 4 + tg] = h;
        Ol[(size_t)grow0 * 64 + nt * 4 + tg] = l;
        bf16_split2(v2, v3, h, l);
        Oh[(size_t)grow1 * 64 + nt * 4 + tg] = h;
        Ol[(size_t)grow1 * 64 + nt * 4 + tg] = l;
    }
}

// =============================================================================
// Fused out_proj: x1 = att @ opw^T + opb + norm(x0), plus ssq partials of x1
// =============================================================================
__global__ void __launch_bounds__(256, 1) k_oproj(
    const float* __restrict__ att, const float* __restrict__ opw,
    const float* __restrict__ opb, const float* __restrict__ x0,
    const float* __restrict__ rms, float* __restrict__ x1)
{
    extern __shared__ uint32_t smw[];
    uint32_t* Ah = smw;
    uint32_t* Al = Ah + 128 * P;
    uint32_t* Wh = Al + 128 * P;
    uint32_t* Wl = Wh + 128 * P;
    float* bias_s = (float*)(Wl + 128 * P);
    float* red = bias_s + 128;

    int tid = threadIdx.x;
    int rowBase = blockIdx.x * 128;
    float inv = g_inv[rowBase >> 11];
    if (tid < 128) bias_s[tid] = opb[tid];

    #pragma unroll
    for (int i = 0; i < 16; i++) {
        int f = tid + i * 256;
        int row = f >> 5, q4 = f & 31;
        float4 xv = *(const float4*)(att + (size_t)(rowBase + row) * 128 + q4 * 4);
        stage4(Ah, Al, row * P + q4 * 2, xv.x, xv.y, xv.z, xv.w);
        float4 wv = *(const float4*)(opw + (size_t)row * 128 + q4 * 4);
        stage4(Wh, Wl, row * P + q4 * 2, wv.x, wv.y, wv.z, wv.w);
    }
    __syncthreads();

    int w = tid >> 5, lane = tid & 31, g = lane >> 2, tg = lane & 3;
    int r0 = w * 16 + g, r1 = r0 + 8;

    float acc[16][4];
    #pragma unroll
    for (int nt = 0; nt < 16; nt++)
        #pragma unroll
        for (int e = 0; e < 4; e++) acc[nt][e] = 0.f;

    #pragma unroll
    for (int kg = 0; kg < 8; kg++) {
        int b0 = kg * 8 + tg;
        uint32_t ah[4], al[4];
        ah[0] = Ah[r0 * P + b0];     ah[1] = Ah[r1 * P + b0];
        ah[2] = Ah[r0 * P + b0 + 4]; ah[3] = Ah[r1 * P + b0 + 4];
        al[0] = Al[r0 * P + b0];     al[1] = Al[r1 * P + b0];
        al[2] = Al[r0 * P + b0 + 4]; al[3] = Al[r1 * P + b0 + 4];
        #pragma unroll
        for (int nt = 0; nt < 16; nt++) {
            int n = nt * 8 + g;
            uint32_t bh0 = Wh[n * P + b0], bh1 = Wh[n * P + b0 + 4];
            uint32_t bl0 = Wl[n * P + b0], bl1 = Wl[n * P + b0 + 4];
            mma_bf16(acc[nt], ah, bh0, bh1);
            mma_bf16(acc[nt], al, bh0, bh1);
            mma_bf16(acc[nt], ah, bl0, bl1);
        }
    }

    int grow0 = rowBase + r0, grow1 = rowBase + r1;
    int m0 = grow0 & (Mm - 1), m1 = grow1 & (Mm - 1);
    float ssq = 0.f;
    #pragma unroll
    for (int nt = 0; nt < 16; nt++) {
        int col = nt * 8 + 2 * tg;
        float2 xa = *(const float2*)(x0 + (size_t)grow0 * 128 + col);
        float2 sa = *(const float2*)(rms + (size_t)m0 * 128 + col);
        float2 xb = *(const float2*)(x0 + (size_t)grow1 * 128 + col);
        float2 sb = *(const float2*)(rms + (size_t)m1 * 128 + col);
        float v0 = acc[nt][0] + bias_s[col]     + xa.x * inv * sa.x;
        float v1 = acc[nt][1] + bias_s[col + 1] + xa.y * inv * sa.y;
        float v2 = acc[nt][2] + bias_s[col]     + xb.x * inv * sb.x;
        float v3 = acc[nt][3] + bias_s[col + 1] + xb.y * inv * sb.y;
        float2 o0; o0.x = v0; o0.y = v1;
        float2 o1; o1.x = v2; o1.y = v3;
        *(float2*)(x1 + (size_t)grow0 * 128 + col) = o0;
        *(float2*)(x1 + (size_t)grow1 * 128 + col) = o1;
        ssq += v0 * v0 + v1 * v1 + v2 * v2 + v3 * v3;
    }

    red[tid] = ssq;
    __syncthreads();
    for (int s = 128; s > 0; s >>= 1) {
        if (tid < s) red[tid] += red[tid + s];
        __syncthreads();
    }
    if (tid == 0) g_part2[blockIdx.x] = red[0];
}

// =============================================================================
// Fused MLP + logits + loss partials:
// x2 = norm(x1); x3 = x2 + relu(x2@lw^T+lb); logits = x3@ow^T+ob; nll partials
// =============================================================================
__global__ void __launch_bounds__(256, 1) k_mlp(
    const float* __restrict__ x1, const float* __restrict__ rms,
    const float* __restrict__ lw, const float* __restrict__ lb,
    const float* __restrict__ ow, const float* __restrict__ ob,
    const int* __restrict__ tgt, float* __restrict__ out)
{
    extern __shared__ uint32_t smw[];
    uint32_t* Ah = smw;
    uint32_t* Al = Ah + 128 * P;
    uint32_t* Wh = Al + 128 * P;
    uint32_t* Wl = Wh + 128 * P;
    float* biasl = (float*)(Wl + 128 * P);   // 128
    float* biaso = biasl + 128;              // 32
    float* red   = biaso + 32;               // 64

    int tid = threadIdx.x;
    int rowBase = blockIdx.x * 128;
    float inv = g_inv2[rowBase >> 11];
    if (tid < 128) biasl[tid] = lb[tid];
    if (tid >= 128 && tid < 160) biaso[tid - 128] = ob[tid - 128];

    #pragma unroll
    for (int i = 0; i < 16; i++) {
        int f = tid + i * 256;
        int row = f >> 5, q4 = f & 31;
        int m = (rowBase + row) & (Mm - 1);
        float4 xv = *(const float4*)(x1 + (size_t)(rowBase + row) * 128 + q4 * 4);
        float4 sv = *(const float4*)(rms + (size_t)m * 128 + q4 * 4);
        stage4(Ah, Al, row * P + q4 * 2,
               xv.x * inv * sv.x, xv.y * inv * sv.y,
               xv.z * inv * sv.z, xv.w * inv * sv.w);
        float4 wv = *(const float4*)(lw + (size_t)row * 128 + q4 * 4);
        stage4(Wh, Wl, row * P + q4 * 2, wv.x, wv.y, wv.z, wv.w);
    }
    __syncthreads();

    int w = tid >> 5, lane = tid & 31, g = lane >> 2, tg = lane & 3;
    int r0 = w * 16 + g, r1 = r0 + 8;

    // ---- GEMM1 (lin)
    float acc[16][4];
    #pragma unroll
    for (int nt = 0; nt < 16; nt++)
        #pragma unroll
        for (int e = 0; e < 4; e++) acc[nt][e] = 0.f;

    #pragma unroll
    for (int kg = 0; kg < 8; kg++) {
        int b0 = kg * 8 + tg;
        uint32_t ah[4], al[4];
        ah[0] = Ah[r0 * P + b0];     ah[1] = Ah[r1 * P + b0];
        ah[2] = Ah[r0 * P + b0 + 4]; ah[3] = Ah[r1 * P + b0 + 4];
        al[0] = Al[r0 * P + b0];     al[1] = Al[r1 * P + b0];
        al[2] = Al[r0 * P + b0 + 4]; al[3] = Al[r1 * P + b0 + 4];
        #pragma unroll
        for (int nt = 0; nt < 16; nt++) {
            int n = nt * 8 + g;
            uint32_t bh0 = Wh[n * P + b0], bh1 = Wh[n * P + b0 + 4];
            uint32_t bl0 = Wl[n * P + b0], bl1 = Wl[n * P + b0 + 4];
            mma_bf16(acc[nt], ah, bh0, bh1);
            mma_bf16(acc[nt], al, bh0, bh1);
            mma_bf16(acc[nt], ah, bl0, bl1);
        }
    }

    // ---- x3 = x2 + relu(acc + lb)   (x2 reconstructed from staged hi+lo)
    #pragma unroll
    for (int nt = 0; nt < 16; nt++) {
        int wrd = nt * 4 + tg;
        int col = nt * 8 + 2 * tg;
        float2 x2a_h = bf2_unpack(Ah[r0 * P + wrd]);
        float2 x2a_l = bf2_unpack(Al[r0 * P + wrd]);
        float2 x2b_h = bf2_unpack(Ah[r1 * P + wrd]);
        float2 x2b_l = bf2_unpack(Al[r1 * P + wrd]);
        acc[nt][0] = (x2a_h.x + x2a_l.x) + fmaxf(acc[nt][0] + biasl[col],     0.f);
        acc[nt][1] = (x2a_h.y + x2a_l.y) + fmaxf(acc[nt][1] + biasl[col + 1], 0.f);
        acc[nt][2] = (x2b_h.x + x2b_l.x) + fmaxf(acc[nt][2] + biasl[col],     0.f);
        acc[nt][3] = (x2b_h.y + x2b_l.y) + fmaxf(acc[nt][3] + biasl[col + 1], 0.f);
    }

    // ---- repack x3 as A fragments
    uint32_t a2h[8][4], a2l[8][4];
    #pragma unroll
    for (int kg = 0; kg < 8; kg++) {
        bf16_split2(acc[2*kg][0],   acc[2*kg][1],   a2h[kg][0], a2l[kg][0]);
        bf16_split2(acc[2*kg][2],   acc[2*kg][3],   a2h[kg][1], a2l[kg][1]);
        bf16_split2(acc[2*kg+1][0], acc[2*kg+1][1], a2h[kg][2], a2l[kg][2]);
        bf16_split2(acc[2*kg+1][2], acc[2*kg+1][3], a2h[kg][3], a2l[kg][3]);
    }
    __syncthreads();

    // ---- stage ow (32 x 128) into W region
    #pragma unroll
    for (int i = 0; i < 4; i++) {
        int f = tid + i * 256;
        int row = f >> 5, q4 = f & 31;
        float4 wv = *(const float4*)(ow + (size_t)row * 128 + q4 * 4);
        stage4(Wh, Wl, row * P + q4 * 2, wv.x, wv.y, wv.z, wv.w);
    }
    __syncthreads();

    // ---- GEMM2 (logits, N=32)
    int grow0 = rowBase + r0, grow1 = rowBase + r1;
    float L[4][4];
    #pragma unroll
    for (int nt = 0; nt < 4; nt++) {
        float a2[4] = {0.f, 0.f, 0.f, 0.f};
        #pragma unroll
        for (int kg = 0; kg < 8; kg++) {
            int b0 = kg * 8 + tg;
            int n = nt * 8 + g;
            uint32_t bh0 = Wh[n * P + b0], bh1 = Wh[n * P + b0 + 4];
            uint32_t bl0 = Wl[n * P + b0], bl1 = Wl[n * P + b0 + 4];
            mma_bf16(a2, a2h[kg], bh0, bh1);
            mma_bf16(a2, a2l[kg], bh0, bh1);
            mma_bf16(a2, a2h[kg], bl0, bl1);
        }
        int col = nt * 8 + 2 * tg;
        L[nt][0] = a2[0] + biaso[col];
        L[nt][1] = a2[1] + biaso[col + 1];
        L[nt][2] = a2[2] + biaso[col];
        L[nt][3] = a2[3] + biaso[col + 1];
        float2 o0; o0.x = L[nt][0]; o0.y = L[nt][1];
        float2 o1; o1.x = L[nt][2]; o1.y = L[nt][3];
        *(float2*)(out + (size_t)grow0 * 32 + col) = o0;
        *(float2*)(out + (size_t)grow1 * 32 + col) = o1;
    }

    // ---- loss partials (quad tg = lane bits 0..1)
    float mx0 = -1e30f, mx1 = -1e30f;
    #pragma unroll
    for (int nt = 0; nt < 4; nt++) {
        mx0 = fmaxf(mx0, fmaxf(L[nt][0], L[nt][1]));
        mx1 = fmaxf(mx1, fmaxf(L[nt][2], L[nt][3]));
    }
    mx0 = fmaxf(mx0, __shfl_xor_sync(0xffffffffu, mx0, 1));
    mx0 = fmaxf(mx0, __shfl_xor_sync(0xffffffffu, mx0, 2));
    mx1 = fmaxf(mx1, __shfl_xor_sync(0xffffffffu, mx1, 1));
    mx1 = fmaxf(mx1, __shfl_xor_sync(0xffffffffu, mx1, 2));

    int t0 = tgt[grow0], t1 = tgt[grow1];
    float se0 = 0.f, se1 = 0.f, tv0 = -1e30f, tv1 = -1e30f;
    #pragma unroll
    for (int nt = 0; nt < 4; nt++) {
        int col = nt * 8 + 2 * tg;
        se0 += expf(L[nt][0] - mx0) + expf(L[nt][1] - mx0);
        se1 += expf(L[nt][2] - mx1) + expf(L[nt][3] - mx1);
        if (col == t0)     tv0 = L[nt][0];
        if (col + 1 == t0) tv0 = L[nt][1];
        if (col == t1)     tv1 = L[nt][2];
        if (col + 1 == t1) tv1 = L[nt][3];
    }
    se0 += __shfl_xor_sync(0xffffffffu, se0, 1);
    se0 += __shfl_xor_sync(0xffffffffu, se0, 2);
    se1 += __shfl_xor_sync(0xffffffffu, se1, 1);
    se1 += __shfl_xor_sync(0xffffffffu, se1, 2);
    tv0 = fmaxf(tv0, __shfl_xor_sync(0xffffffffu, tv0, 1));
    tv0 = fmaxf(tv0, __shfl_xor_sync(0xffffffffu, tv0, 2));
    tv1 = fmaxf(tv1, __shfl_xor_sync(0xffffffffu, tv1, 1));
    tv1 = fmaxf(tv1, __shfl_xor_sync(0xffffffffu, tv1, 2));

    if (tg == 0) {
        float nll0 = -(tv0 - mx0 - logf(se0));
        float nll1 = -(tv1 - mx1 - logf(se1));
        red[w * 8 + g] = nll0 + nll1;
    }
    __syncthreads();
    for (int s = 32; s > 0; s >>= 1) {
        if (tid < s) red[tid] += red[tid + s];
        __syncthreads();
    }
    if (tid == 0) g_losspart[blockIdx.x] = red[0];
}

// =============================================================================
// mma.sync bf16 flash attention (unchanged from round 4 — passing)
// =============================================================================
__global__ void __launch_bounds__(256, 2) k_attn_mma() {
    int bid = blockIdx.x;
    int qt = 15 - (bid >> 6);
    int bh = bid & 63;
    int b = bh >> 3, h = bh & 7;
    int tid = threadIdx.x;
    int w = tid >> 5, lane = tid & 31;
    int g = lane >> 2, tg = lane & 3;
    int tokbase = b * Mm;
    int qBase = qt * 128 + w * 16;

    __shared__ uint32_t Khi[64*9], Klo[64*9];
    __shared__ uint32_t Vthi[16*36], Vtlo[16*36];

    uint32_t qh[4], ql[4];
    {
        const uint32_t* ph = g_qh + (size_t)(tokbase + qBase) * 64 + h * 8;
        const uint32_t* pl = g_ql + (size_t)(tokbase + qBase) * 64 + h * 8;
        qh[0] = ph[(size_t)g * 64 + tg];
        qh[1] = ph[(size_t)(g + 8) * 64 + tg];
        qh[2] = ph[(size_t)g * 64 + tg + 4];
        qh[3] = ph[(size_t)(g + 8) * 64 + tg + 4];
        ql[0] = pl[(size_t)g * 64 + tg];
        ql[1] = pl[(size_t)(g + 8) * 64 + tg];
        ql[2] = pl[(size_t)g * 64 + tg + 4];
        ql[3] = pl[(size_t)(g + 8) * 64 + tg + 4];
    }

    float o[2][4];
    #pragma unroll
    for (int t = 0; t < 2; t++)
        #pragma unroll
        for (int e = 0; e < 4; e++) o[t][e] = 0.f;
    float m0 = -1e30f, m1 = -1e30f, l0 = 0.f, l1 = 0.f;

    int q0 = qBase + g;
    int q1 = qBase + g + 8;

    int nkt = 2 * qt + 2;
    for (int kt = 0; kt < nkt; kt++) {
        int kb = kt * 64;
        __syncthreads();
        #pragma unroll
        for (int i = 0; i < 2; i++) {
            int wv = tid + i * 256;
            int key = wv >> 3, c = wv & 7;
            size_t ga = (size_t)(tokbase + kb + key) * 64 + h * 8 + c;
            Khi[key * 9 + c] = g_kh[ga];
            Klo[key * 9 + c] = g_kl[ga];
            uint32_t pv = g_vh[ga];
            uint32_t pl = g_vl[ga];
            ((uint16_t*)Vthi)[(2*c    ) * 72 + key] = (uint16_t)(pv & 0xFFFF);
            ((uint16_t*)Vthi)[(2*c + 1) * 72 + key] = (uint16_t)(pv >> 16);
            ((uint16_t*)Vtlo)[(2*c    ) * 72 + key] = (uint16_t)(pl & 0xFFFF);
            ((uint16_t*)Vtlo)[(2*c + 1) * 72 + key] = (uint16_t)(pl >> 16);
        }
        __syncthreads();

        float s[8][4];
        #pragma unroll
        for (int nt = 0; nt < 8; nt++) {
            uint32_t bh0 = Khi[(nt * 8 + g) * 9 + tg];
            uint32_t bh1 = Khi[(nt * 8 + g) * 9 + tg + 4];
            uint32_t bl0 = Klo[(nt * 8 + g) * 9 + tg];
            uint32_t bl1 = Klo[(nt * 8 + g) * 9 + tg + 4];
            #pragma unroll
            for (int e = 0; e < 4; e++) s[nt][e] = 0.f;
            mma_bf16(s[nt], qh, bh0, bh1);
            mma_bf16(s[nt], ql, bh0, bh1);
            mma_bf16(s[nt], qh, bl0, bl1);
        }

        float tmax0 = -1e30f, tmax1 = -1e30f;
        #pragma unroll
        for (int nt = 0; nt < 8; nt++) {
            int kc = kb + nt * 8 + 2 * tg;
            s[nt][0] = (kc     <= q0) ? s[nt][0] * 0.25f : -1e30f;
            s[nt][1] = (kc + 1 <= q0) ? s[nt][1] * 0.25f : -1e30f;
            s[nt][2] = (kc     <= q1) ? s[nt][2] * 0.25f : -1e30f;
            s[nt][3] = (kc + 1 <= q1) ? s[nt][3] * 0.25f : -1e30f;
            tmax0 = fmaxf(tmax0, fmaxf(s[nt][0], s[nt][1]));
            tmax1 = fmaxf(tmax1, fmaxf(s[nt][2], s[nt][3]));
        }
        tmax0 = fmaxf(tmax0, __shfl_xor_sync(0xffffffffu, tmax0, 1));
        tmax0 = fmaxf(tmax0, __shfl_xor_sync(0xffffffffu, tmax0, 2));
        tmax1 = fmaxf(tmax1, __shfl_xor_sync(0xffffffffu, tmax1, 1));
        tmax1 = fmaxf(tmax1, __shfl_xor_sync(0xffffffffu, tmax1, 2));

        float mn0 = fmaxf(m0, tmax0), mn1 = fmaxf(m1, tmax1);
        float a0 = __expf(m0 - mn0), a1 = __expf(m1 - mn1);
        m0 = mn0; m1 = mn1;
        l0 *= a0; l1 *= a1;
        #pragma unroll
        for (int t = 0; t < 2; t++) {
            o[t][0] *= a0; o[t][1] *= a0; o[t][2] *= a1; o[t][3] *= a1;
        }

        uint32_t phi[8][2], plo[8][2];
        #pragma unroll
        for (int nt = 0; nt < 8; nt++) {
            float p0 = __expf(s[nt][0] - mn0);
            float p1 = __expf(s[nt][1] - mn0);
            float p2 = __expf(s[nt][2] - mn1);
            float p3 = __expf(s[nt][3] - mn1);
            l0 += p0 + p1; l1 += p2 + p3;
            bf16_split2(p0, p1, phi[nt][0], plo[nt][0]);
            bf16_split2(p2, p3, phi[nt][1], plo[nt][1]);
        }

        #pragma unroll
        for (int kg = 0; kg < 4; kg++) {
            uint32_t ah[4] = { phi[2*kg][0], phi[2*kg][1], phi[2*kg+1][0], phi[2*kg+1][1] };
            uint32_t al[4] = { plo[2*kg][0], plo[2*kg][1], plo[2*kg+1][0], plo[2*kg+1][1] };
            #pragma unroll
            for (int t = 0; t < 2; t++) {
                int n = t * 8 + g;
                uint32_t bh0 = Vthi[n * 36 + kg * 8 + tg];
                uint32_t bh1 = Vthi[n * 36 + kg * 8 + tg + 4];
                uint32_t bl0 = Vtlo[n * 36 + kg * 8 + tg];
                uint32_t bl1 = Vtlo[n * 36 + kg * 8 + tg + 4];
                mma_bf16(o[t], ah, bh0, bh1);
                mma_bf16(o[t], al, bh0, bh1);
                mma_bf16(o[t], ah, bl0, bl1);
            }
        }
    }

    l0 += __shfl_xor_sync(0xffffffffu, l0, 1);
    l0 += __shfl_xor_sync(0xffffffffu, l0, 2);
    l1 += __shfl_xor_sync(0xffffffffu, l1, 1);
    l1 += __shfl_xor_sync(0xffffffffu, l1, 2);
    float i0 = 1.f / l0, i1 = 1.f / l1;

    #pragma unroll
    for (int t = 0; t < 2; t++) {
        int d = h * HDIM + t * 8 + 2 * tg;
        float2 r0; r0.x = o[t][0] * i0; r0.y = o[t][1] * i0;
        float2 r1; r1.x = o[t][2] * i1; r1.y = o[t][3] * i1;
        *(float2*)(g_att + (size_t)(tokbase + q0) * 128 + d) = r0;
        *(float2*)(g_att + (size_t)(tokbase + q1) * 128 + d) = r1;
    }
}

// ----------------------------- small kernels ----------------------------------
__global__ void k_rope_tables() {
    int i   = threadIdx.x;
    int pos = blockIdx.x;
    float base = powf(10000.0f, -2.0f * ((float)i - 1.0f) / 128.0f);
    float ang  = (float)pos * base;
    float s, c;
    sincosf(ang, &s, &c);
    g_cos[pos*64 + i] = c;
    g_sin[pos*64 + i] = s;
}

__global__ void __launch_bounds__(256) k_embed(const int* __restrict__ idx,
                                               const float* __restrict__ emb) {
    int b   = blockIdx.x;
    int seg = blockIdx.y;
    int tid = threadIdx.x;
    int tok0 = seg * 16;
    float ss = 0.f;
    #pragma unroll
    for (int e = 0; e < 8; e++) {
        int li = tid + e * 256;
        int t  = tok0 + (li >> 7);
        int d  = li & 127;
        int row = idx[b*Mm + t];
        float vv = emb[row*Dd + d];
        g_x0[((size_t)(b*Mm + t))*Dd + d] = vv;
        ss += vv * vv;
    }
    __shared__ float red[256];
    red[tid] = ss; __syncthreads();
    for (int s = 128; s > 0; s >>= 1) {
        if (tid < s) red[tid] += red[tid + s];
        __syncthreads();
    }
    if (tid == 0) g_part[b*128 + seg] = red[0];
}

__global__ void k_inv() {
    int b = blockIdx.x;
    int tid = threadIdx.x;
    __shared__ float red[128];
    red[tid] = g_part[b*128 + tid]; __syncthreads();
    for (int s = 64; s > 0; s >>= 1) {
        if (tid < s) red[tid] += red[tid + s];
        __syncthreads();
    }
    if (tid == 0) g_inv[b] = 512.0f / sqrtf(red[0]);
}

__global__ void k_inv2() {
    int b = blockIdx.x;
    int tid = threadIdx.x;     // 16
    __shared__ float red[16];
    red[tid] = g_part2[b*16 + tid]; __syncthreads();
    for (int s = 8; s > 0; s >>= 1) {
        if (tid < s) red[tid] += red[tid + s];
        __syncthreads();
    }
    if (tid == 0) g_inv2[b] = 512.0f / sqrtf(red[0]);
}

__global__ void k_lossfin(float* out) {
    int tid = threadIdx.x;     // 128
    __shared__ float red[128];
    red[tid] = g_losspart[tid]; __syncthreads();
    for (int s = 64; s > 0; s >>= 1) {
        if (tid < s) red[tid] += red[tid + s];
        __syncthreads();
    }
    if (tid == 0) out[0] = red[0] / (float)TOK;
}

// ----------------------------- host driver -----------------------------------
extern "C" void kernel_launch(void* const* d_in, const int* in_sizes, int n_in,
                              void* d_out, int out_size) {
    const int*   idx = (const int*)  d_in[0];
    const int*   tgt = (const int*)  d_in[1];
    const float* emb = (const float*)d_in[2];
    const float* rms = (const float*)d_in[3];
    const float* Wq  = (const float*)d_in[4];
    const float* Wk  = (const float*)d_in[5];
    const float* Wv  = (const float*)d_in[6];
    const float* inw = (const float*)d_in[7];
    const float* inb = (const float*)d_in[8];
    const float* opw = (const float*)d_in[9];
    const float* opb = (const float*)d_in[10];
    const float* lw  = (const float*)d_in[11];
    const float* lb  = (const float*)d_in[12];
    const float* ow  = (const float*)d_in[13];
    const float* ob  = (const float*)d_in[14];
    float* out = (float*)d_out;

    float *x0, *att, *x1;
    uint32_t *qh, *ql, *kh, *kl, *vh, *vl;
    cudaGetSymbolAddress((void**)&x0,  g_x0);
    cudaGetSymbolAddress((void**)&att, g_att);
    cudaGetSymbolAddress((void**)&x1,  g_x1);
    cudaGetSymbolAddress((void**)&qh,  g_qh);
    cudaGetSymbolAddress((void**)&ql,  g_ql);
    cudaGetSymbolAddress((void**)&kh,  g_kh);
    cudaGetSymbolAddress((void**)&kl,  g_kl);
    cudaGetSymbolAddress((void**)&vh,  g_vh);
    cudaGetSymbolAddress((void**)&vl,  g_vl);

    const int PLANES = 4 * 128 * P * 4;            // 139264 bytes
    const int SMQ = PLANES + 128 * 4;              // + bias
    const int SMO = PLANES + 128 * 4 + 256 * 4;    // + bias + red
    const int SMM = PLANES + 128 * 4 + 32 * 4 + 64 * 4;
    cudaFuncSetAttribute(k_qkv,   cudaFuncAttributeMaxDynamicSharedMemorySize, SMQ);
    cudaFuncSetAttribute(k_oproj, cudaFuncAttributeMaxDynamicSharedMemorySize, SMO);
    cudaFuncSetAttribute(k_mlp,   cudaFuncAttributeMaxDynamicSharedMemorySize, SMM);

    k_rope_tables<<<Mm, 64>>>();
    k_embed<<<dim3(Bb, 128), 256>>>(idx, emb);
    k_inv<<<Bb, 128>>>();

    k_qkv<<<dim3(128, 3), 256, SMQ>>>(x0, rms, Wq, Wk, Wv, inw, inb,
                                      qh, ql, kh, kl, vh, vl);

    k_attn_mma<<<1024, 256>>>();

    k_oproj<<<128, 256, SMO>>>(att, opw, opb, x0, rms, x1);
    k_inv2<<<Bb, 16>>>();

    k_mlp<<<128, 256, SMM>>>(x1, rms, lw, lb, ow, ob, tgt, out);

    if (out_size > TOK*Vv) k_lossfin<<<1, 128>>>(out + (size_t)TOK*Vv);
}

// round 6
// speedup vs baseline: 3.2930x; 1.0560x over previous
#include <cuda_runtime.h>
#include <cuda_bf16.h>
#include <math.h>
#include <stdint.h>

#define Bb 8
#define Mm 2048
#define Dd 128
#define HDIM 16
#define Vv 32
#define TOK (Bb*Mm)          // 16384
#define SLAB (Mm*Dd)
#define P 68                 // smem word pitch for GEMM planes
#define KP 12                // smem word pitch for attention K/V tiles

// ----------------------------- scratch ---------------------------------------
__device__ float g_x0[TOK*Dd];
__device__ float g_att[TOK*Dd];
__device__ float g_x1[TOK*Dd];
__device__ uint32_t g_qh[TOK*64];
__device__ uint32_t g_ql[TOK*64];
__device__ uint32_t g_kh[TOK*64];
__device__ uint32_t g_kl[TOK*64];
__device__ uint32_t g_vh[TOK*64];
__device__ uint32_t g_vl[TOK*64];
__device__ float g_cos[Mm*64];
__device__ float g_sin[Mm*64];
__device__ float g_part[Bb*128];
__device__ float g_part2[128];
__device__ float g_inv[Bb];
__device__ float g_inv2[Bb];
__device__ float g_losspart[128];

// ----------------------------- helpers ----------------------------------------
__device__ __forceinline__ uint32_t s_addr(const void* p) {
    uint32_t a;
    asm("{ .reg .u64 t; cvta.to.shared.u64 t, %1; cvt.u32.u64 %0, t; }"
        : "=r"(a) : "l"(p));
    return a;
}
__device__ __forceinline__ void ldsm4(uint32_t r[4], uint32_t addr) {
    asm volatile("ldmatrix.sync.aligned.m8n8.x4.shared.b16 {%0,%1,%2,%3}, [%4];"
        : "=r"(r[0]), "=r"(r[1]), "=r"(r[2]), "=r"(r[3]) : "r"(addr));
}
__device__ __forceinline__ void ldsm4t(uint32_t r[4], uint32_t addr) {
    asm volatile("ldmatrix.sync.aligned.m8n8.x4.trans.shared.b16 {%0,%1,%2,%3}, [%4];"
        : "=r"(r[0]), "=r"(r[1]), "=r"(r[2]), "=r"(r[3]) : "r"(addr));
}
__device__ __forceinline__ void mma_bf16(float c[4], const uint32_t a[4],
                                         uint32_t b0, uint32_t b1) {
    asm volatile(
        "mma.sync.aligned.m16n8k16.row.col.f32.bf16.bf16.f32 "
        "{%0,%1,%2,%3}, {%4,%5,%6,%7}, {%8,%9}, {%0,%1,%2,%3};"
        : "+f"(c[0]), "+f"(c[1]), "+f"(c[2]), "+f"(c[3])
        : "r"(a[0]), "r"(a[1]), "r"(a[2]), "r"(a[3]), "r"(b0), "r"(b1));
}
__device__ __forceinline__ void bf16_split2(float x, float y,
                                            uint32_t& hi, uint32_t& lo) {
    __nv_bfloat162 hb = __float22bfloat162_rn(make_float2(x, y));
    float2 back = __bfloat1622float2(hb);
    __nv_bfloat162 lb = __float22bfloat162_rn(make_float2(x - back.x, y - back.y));
    hi = *(uint32_t*)&hb;
    lo = *(uint32_t*)&lb;
}
__device__ __forceinline__ float2 bf2_unpack(uint32_t w) {
    __nv_bfloat162 t;
    *(uint32_t*)&t = w;
    return __bfloat1622float2(t);
}
__device__ __forceinline__ void stage4(uint32_t* H, uint32_t* L, int idx,
                                       float a, float b, float c, float d) {
    uint32_t h0, l0, h1, l1;
    bf16_split2(a, b, h0, l0);
    bf16_split2(c, d, h1, l1);
    H[idx] = h0; H[idx + 1] = h1;
    L[idx] = l0; L[idx + 1] = l1;
}

// 3-term bf16 mma pair over an nt-pair (even/odd) given B frag quads
#define MMA6(accE, accO, ah, al, bh, bl)            \
    do {                                            \
        mma_bf16(accE, ah, (bh)[0], (bh)[2]);       \
        mma_bf16(accE, al, (bh)[0], (bh)[2]);       \
        mma_bf16(accE, ah, (bl)[0], (bl)[2]);       \
        mma_bf16(accO, ah, (bh)[1], (bh)[3]);       \
        mma_bf16(accO, al, (bh)[1], (bh)[3]);       \
        mma_bf16(accO, ah, (bl)[1], (bl)[3]);       \
    } while (0)

// =============================================================================
// Fused QKV: C1 = norm(x0) @ Wsel^T ; rope(C1) ; out = C1r @ inw_sel^T + b
// =============================================================================
__global__ void __launch_bounds__(256, 1) k_qkv(
    const float* __restrict__ x0, const float* __restrict__ rms,
    const float* __restrict__ Wq, const float* __restrict__ Wk,
    const float* __restrict__ Wv,
    const float* __restrict__ inw, const float* __restrict__ inb,
    uint32_t* __restrict__ qh_, uint32_t* __restrict__ ql_,
    uint32_t* __restrict__ kh_, uint32_t* __restrict__ kl_,
    uint32_t* __restrict__ vh_, uint32_t* __restrict__ vl_)
{
    extern __shared__ uint32_t smw[];
    uint32_t* Ah = smw;
    uint32_t* Al = Ah + 128 * P;
    uint32_t* Wh = Al + 128 * P;
    uint32_t* Wl = Wh + 128 * P;
    float* bias_s = (float*)(Wl + 128 * P);

    int which = blockIdx.y;
    const float* W1 = (which == 0) ? Wq : ((which == 1) ? Wk : Wv);
    const float* W2 = inw + which * (Dd * Dd);
    uint32_t* Oh = (which == 0) ? qh_ : ((which == 1) ? kh_ : vh_);
    uint32_t* Ol = (which == 0) ? ql_ : ((which == 1) ? kl_ : vl_);

    int tid = threadIdx.x;
    int rowBase = blockIdx.x * 128;
    float inv = g_inv[rowBase >> 11];
    if (tid < 128) bias_s[tid] = inb[which * 128 + tid];

    #pragma unroll
    for (int i = 0; i < 16; i++) {
        int f = tid + i * 256;
        int row = f >> 5, q4 = f & 31;
        int m = (rowBase + row) & (Mm - 1);
        float4 xv = *(const float4*)(x0 + (size_t)(rowBase + row) * 128 + q4 * 4);
        float4 sv = *(const float4*)(rms + (size_t)m * 128 + q4 * 4);
        stage4(Ah, Al, row * P + q4 * 2,
               xv.x * inv * sv.x, xv.y * inv * sv.y,
               xv.z * inv * sv.z, xv.w * inv * sv.w);
        float4 wv = *(const float4*)(W1 + (size_t)row * 128 + q4 * 4);
        stage4(Wh, Wl, row * P + q4 * 2, wv.x, wv.y, wv.z, wv.w);
    }
    __syncthreads();

    int w = tid >> 5, lane = tid & 31, g = lane >> 2, tg = lane & 3;
    int r0 = w * 16 + g, r1 = r0 + 8;
    int lrow = lane & 15;            // ldmatrix row within 16-row tile
    int lcol = (lane >> 4) * 4;      // word offset 0/4
    uint32_t aoff = ((uint32_t)(w * 16 + lrow) * P + lcol) * 4;
    uint32_t boff = ((uint32_t)lrow * P + lcol) * 4;
    uint32_t adA_h = s_addr(Ah) + aoff, adA_l = s_addr(Al) + aoff;
    uint32_t adW_h = s_addr(Wh) + boff, adW_l = s_addr(Wl) + boff;

    // ---- GEMM1
    float acc[16][4];
    #pragma unroll
    for (int nt = 0; nt < 16; nt++)
        #pragma unroll
        for (int e = 0; e < 4; e++) acc[nt][e] = 0.f;

    #pragma unroll
    for (int kg = 0; kg < 8; kg++) {
        uint32_t ah[4], al[4];
        ldsm4(ah, adA_h + kg * 32);
        ldsm4(al, adA_l + kg * 32);
        #pragma unroll
        for (int ntp = 0; ntp < 8; ntp++) {
            uint32_t bh[4], bl[4];
            ldsm4(bh, adW_h + (uint32_t)ntp * (16 * P * 4) + kg * 32);
            ldsm4(bl, adW_l + (uint32_t)ntp * (16 * P * 4) + kg * 32);
            MMA6(acc[2*ntp], acc[2*ntp+1], ah, al, bh, bl);
        }
    }

    // ---- RoPE in registers
    int m0 = (rowBase + r0) & (Mm - 1), m1 = (rowBase + r1) & (Mm - 1);
    #pragma unroll
    for (int nt = 0; nt < 16; nt++) {
        int i = nt * 4 + tg;
        float c0 = g_cos[m0 * 64 + i], s0 = g_sin[m0 * 64 + i];
        float c1 = g_cos[m1 * 64 + i], s1 = g_sin[m1 * 64 + i];
        float te = acc[nt][0], to = acc[nt][1];
        acc[nt][0] =  te * c0 + to * s0;
        acc[nt][1] = -te * s0 + to * c0;
        te = acc[nt][2]; to = acc[nt][3];
        acc[nt][2] =  te * c1 + to * s1;
        acc[nt][3] = -te * s1 + to * c1;
    }

    // ---- repack C1 as GEMM2 A fragments
    uint32_t a2h[8][4], a2l[8][4];
    #pragma unroll
    for (int kg = 0; kg < 8; kg++) {
        bf16_split2(acc[2*kg][0],   acc[2*kg][1],   a2h[kg][0], a2l[kg][0]);
        bf16_split2(acc[2*kg][2],   acc[2*kg][3],   a2h[kg][1], a2l[kg][1]);
        bf16_split2(acc[2*kg+1][0], acc[2*kg+1][1], a2h[kg][2], a2l[kg][2]);
        bf16_split2(acc[2*kg+1][2], acc[2*kg+1][3], a2h[kg][3], a2l[kg][3]);
    }
    __syncthreads();

    // ---- stage W2 into A region
    #pragma unroll
    for (int i = 0; i < 16; i++) {
        int f = tid + i * 256;
        int row = f >> 5, q4 = f & 31;
        float4 wv = *(const float4*)(W2 + (size_t)row * 128 + q4 * 4);
        stage4(Ah, Al, row * P + q4 * 2, wv.x, wv.y, wv.z, wv.w);
    }
    __syncthreads();

    // ---- GEMM2 (B = W2 in Ah/Al region)
    uint32_t adB_h = s_addr(Ah) + boff, adB_l = s_addr(Al) + boff;
    #pragma unroll
    for (int nt = 0; nt < 16; nt++)
        #pragma unroll
        for (int e = 0; e < 4; e++) acc[nt][e] = 0.f;

    #pragma unroll
    for (int kg = 0; kg < 8; kg++) {
        #pragma unroll
        for (int ntp = 0; ntp < 8; ntp++) {
            uint32_t bh[4], bl[4];
            ldsm4(bh, adB_h + (uint32_t)ntp * (16 * P * 4) + kg * 32);
            ldsm4(bl, adB_l + (uint32_t)ntp * (16 * P * 4) + kg * 32);
            MMA6(acc[2*ntp], acc[2*ntp+1], a2h[kg], a2l[kg], bh, bl);
        }
    }

    int grow0 = rowBase + r0, grow1 = rowBase + r1;
    #pragma unroll
    for (int nt = 0; nt < 16; nt++) {
        int col = nt * 8 + 2 * tg;
        float v0 = acc[nt][0] + bias_s[col], v1 = acc[nt][1] + bias_s[col + 1];
        float v2 = acc[nt][2] + bias_s[col], v3 = acc[nt][3] + bias_s[col + 1];
        uint32_t h, l;
        bf16_split2(v0, v1, h, l);
        Oh[(size_t)grow0 * 64 + nt * 4 + tg] = h;
        Ol[(size_t)grow0 * 64 + nt * 4 + tg] = l;
        bf16_split2(v2, v3, h, l);
        Oh[(size_t)grow1 * 64 + nt * 4 + tg] = h;
        Ol[(size_t)grow1 * 64 + nt * 4 + tg] = l;
    }
}

// =============================================================================
// Fused out_proj: x1 = att @ opw^T + opb + norm(x0), plus ssq partials
// =============================================================================
__global__ void __launch_bounds__(256, 1) k_oproj(
    const float* __restrict__ att, const float* __restrict__ opw,
    const float* __restrict__ opb, const float* __restrict__ x0,
    const float* __restrict__ rms, float* __restrict__ x1)
{
    extern __shared__ uint32_t smw[];
    uint32_t* Ah = smw;
    uint32_t* Al = Ah + 128 * P;
    uint32_t* Wh = Al + 128 * P;
    uint32_t* Wl = Wh + 128 * P;
    float* bias_s = (float*)(Wl + 128 * P);
    float* red = bias_s + 128;

    int tid = threadIdx.x;
    int rowBase = blockIdx.x * 128;
    float inv = g_inv[rowBase >> 11];
    if (tid < 128) bias_s[tid] = opb[tid];

    #pragma unroll
    for (int i = 0; i < 16; i++) {
        int f = tid + i * 256;
        int row = f >> 5, q4 = f & 31;
        float4 xv = *(const float4*)(att + (size_t)(rowBase + row) * 128 + q4 * 4);
        stage4(Ah, Al, row * P + q4 * 2, xv.x, xv.y, xv.z, xv.w);
        float4 wv = *(const float4*)(opw + (size_t)row * 128 + q4 * 4);
        stage4(Wh, Wl, row * P + q4 * 2, wv.x, wv.y, wv.z, wv.w);
    }
    __syncthreads();

    int w = tid >> 5, lane = tid & 31, g = lane >> 2, tg = lane & 3;
    int r0 = w * 16 + g, r1 = r0 + 8;
    int lrow = lane & 15;
    int lcol = (lane >> 4) * 4;
    uint32_t aoff = ((uint32_t)(w * 16 + lrow) * P + lcol) * 4;
    uint32_t boff = ((uint32_t)lrow * P + lcol) * 4;
    uint32_t adA_h = s_addr(Ah) + aoff, adA_l = s_addr(Al) + aoff;
    uint32_t adW_h = s_addr(Wh) + boff, adW_l = s_addr(Wl) + boff;

    float acc[16][4];
    #pragma unroll
    for (int nt = 0; nt < 16; nt++)
        #pragma unroll
        for (int e = 0; e < 4; e++) acc[nt][e] = 0.f;

    #pragma unroll
    for (int kg = 0; kg < 8; kg++) {
        uint32_t ah[4], al[4];
        ldsm4(ah, adA_h + kg * 32);
        ldsm4(al, adA_l + kg * 32);
        #pragma unroll
        for (int ntp = 0; ntp < 8; ntp++) {
            uint32_t bh[4], bl[4];
            ldsm4(bh, adW_h + (uint32_t)ntp * (16 * P * 4) + kg * 32);
            ldsm4(bl, adW_l + (uint32_t)ntp * (16 * P * 4) + kg * 32);
            MMA6(acc[2*ntp], acc[2*ntp+1], ah, al, bh, bl);
        }
    }

    int grow0 = rowBase + r0, grow1 = rowBase + r1;
    int m0 = grow0 & (Mm - 1), m1 = grow1 & (Mm - 1);
    float ssq = 0.f;
    #pragma unroll
    for (int nt = 0; nt < 16; nt++) {
        int col = nt * 8 + 2 * tg;
        float2 xa = *(const float2*)(x0 + (size_t)grow0 * 128 + col);
        float2 sa = *(const float2*)(rms + (size_t)m0 * 128 + col);
        float2 xb = *(const float2*)(x0 + (size_t)grow1 * 128 + col);
        float2 sb = *(const float2*)(rms + (size_t)m1 * 128 + col);
        float v0 = acc[nt][0] + bias_s[col]     + xa.x * inv * sa.x;
        float v1 = acc[nt][1] + bias_s[col + 1] + xa.y * inv * sa.y;
        float v2 = acc[nt][2] + bias_s[col]     + xb.x * inv * sb.x;
        float v3 = acc[nt][3] + bias_s[col + 1] + xb.y * inv * sb.y;
        float2 o0; o0.x = v0; o0.y = v1;
        float2 o1; o1.x = v2; o1.y = v3;
        *(float2*)(x1 + (size_t)grow0 * 128 + col) = o0;
        *(float2*)(x1 + (size_t)grow1 * 128 + col) = o1;
        ssq += v0 * v0 + v1 * v1 + v2 * v2 + v3 * v3;
    }

    red[tid] = ssq;
    __syncthreads();
    for (int s = 128; s > 0; s >>= 1) {
        if (tid < s) red[tid] += red[tid + s];
        __syncthreads();
    }
    if (tid == 0) g_part2[blockIdx.x] = red[0];
}

// =============================================================================
// Fused MLP + logits + loss partials
// =============================================================================
__global__ void __launch_bounds__(256, 1) k_mlp(
    const float* __restrict__ x1, const float* __restrict__ rms,
    const float* __restrict__ lw, const float* __restrict__ lb,
    const float* __restrict__ ow, const float* __restrict__ ob,
    const int* __restrict__ tgt, float* __restrict__ out)
{
    extern __shared__ uint32_t smw[];
    uint32_t* Ah = smw;
    uint32_t* Al = Ah + 128 * P;
    uint32_t* Wh = Al + 128 * P;
    uint32_t* Wl = Wh + 128 * P;
    float* biasl = (float*)(Wl + 128 * P);
    float* biaso = biasl + 128;
    float* red   = biaso + 32;

    int tid = threadIdx.x;
    int rowBase = blockIdx.x * 128;
    float inv = g_inv2[rowBase >> 11];
    if (tid < 128) biasl[tid] = lb[tid];
    if (tid >= 128 && tid < 160) biaso[tid - 128] = ob[tid - 128];

    #pragma unroll
    for (int i = 0; i < 16; i++) {
        int f = tid + i * 256;
        int row = f >> 5, q4 = f & 31;
        int m = (rowBase + row) & (Mm - 1);
        float4 xv = *(const float4*)(x1 + (size_t)(rowBase + row) * 128 + q4 * 4);
        float4 sv = *(const float4*)(rms + (size_t)m * 128 + q4 * 4);
        stage4(Ah, Al, row * P + q4 * 2,
               xv.x * inv * sv.x, xv.y * inv * sv.y,
               xv.z * inv * sv.z, xv.w * inv * sv.w);
        float4 wv = *(const float4*)(lw + (size_t)row * 128 + q4 * 4);
        stage4(Wh, Wl, row * P + q4 * 2, wv.x, wv.y, wv.z, wv.w);
    }
    __syncthreads();

    int w = tid >> 5, lane = tid & 31, g = lane >> 2, tg = lane & 3;
    int r0 = w * 16 + g, r1 = r0 + 8;
    int lrow = lane & 15;
    int lcol = (lane >> 4) * 4;
    uint32_t aoff = ((uint32_t)(w * 16 + lrow) * P + lcol) * 4;
    uint32_t boff = ((uint32_t)lrow * P + lcol) * 4;
    uint32_t adA_h = s_addr(Ah) + aoff, adA_l = s_addr(Al) + aoff;
    uint32_t adW_h = s_addr(Wh) + boff, adW_l = s_addr(Wl) + boff;

    float acc[16][4];
    #pragma unroll
    for (int nt = 0; nt < 16; nt++)
        #pragma unroll
        for (int e = 0; e < 4; e++) acc[nt][e] = 0.f;

    #pragma unroll
    for (int kg = 0; kg < 8; kg++) {
        uint32_t ah[4], al[4];
        ldsm4(ah, adA_h + kg * 32);
        ldsm4(al, adA_l + kg * 32);
        #pragma unroll
        for (int ntp = 0; ntp < 8; ntp++) {
            uint32_t bh[4], bl[4];
            ldsm4(bh, adW_h + (uint32_t)ntp * (16 * P * 4) + kg * 32);
            ldsm4(bl, adW_l + (uint32_t)ntp * (16 * P * 4) + kg * 32);
            MMA6(acc[2*ntp], acc[2*ntp+1], ah, al, bh, bl);
        }
    }

    // ---- x3 = x2 + relu(acc + lb)
    #pragma unroll
    for (int nt = 0; nt < 16; nt++) {
        int wrd = nt * 4 + tg;
        int col = nt * 8 + 2 * tg;
        float2 x2a_h = bf2_unpack(Ah[r0 * P + wrd]);
        float2 x2a_l = bf2_unpack(Al[r0 * P + wrd]);
        float2 x2b_h = bf2_unpack(Ah[r1 * P + wrd]);
        float2 x2b_l = bf2_unpack(Al[r1 * P + wrd]);
        acc[nt][0] = (x2a_h.x + x2a_l.x) + fmaxf(acc[nt][0] + biasl[col],     0.f);
        acc[nt][1] = (x2a_h.y + x2a_l.y) + fmaxf(acc[nt][1] + biasl[col + 1], 0.f);
        acc[nt][2] = (x2b_h.x + x2b_l.x) + fmaxf(acc[nt][2] + biasl[col],     0.f);
        acc[nt][3] = (x2b_h.y + x2b_l.y) + fmaxf(acc[nt][3] + biasl[col + 1], 0.f);
    }

    uint32_t a2h[8][4], a2l[8][4];
    #pragma unroll
    for (int kg = 0; kg < 8; kg++) {
        bf16_split2(acc[2*kg][0],   acc[2*kg][1],   a2h[kg][0], a2l[kg][0]);
        bf16_split2(acc[2*kg][2],   acc[2*kg][3],   a2h[kg][1], a2l[kg][1]);
        bf16_split2(acc[2*kg+1][0], acc[2*kg+1][1], a2h[kg][2], a2l[kg][2]);
        bf16_split2(acc[2*kg+1][2], acc[2*kg+1][3], a2h[kg][3], a2l[kg][3]);
    }
    __syncthreads();

    #pragma unroll
    for (int i = 0; i < 4; i++) {
        int f = tid + i * 256;
        int row = f >> 5, q4 = f & 31;
        float4 wv = *(const float4*)(ow + (size_t)row * 128 + q4 * 4);
        stage4(Wh, Wl, row * P + q4 * 2, wv.x, wv.y, wv.z, wv.w);
    }
    __syncthreads();

    // ---- GEMM2 (logits, N=32 -> ntp 0..1)
    int grow0 = rowBase + r0, grow1 = rowBase + r1;
    float L[4][4];
    #pragma unroll
    for (int nt = 0; nt < 4; nt++)
        #pragma unroll
        for (int e = 0; e < 4; e++) L[nt][e] = 0.f;

    #pragma unroll
    for (int kg = 0; kg < 8; kg++) {
        #pragma unroll
        for (int ntp = 0; ntp < 2; ntp++) {
            uint32_t bh[4], bl[4];
            ldsm4(bh, adW_h + (uint32_t)ntp * (16 * P * 4) + kg * 32);
            ldsm4(bl, adW_l + (uint32_t)ntp * (16 * P * 4) + kg * 32);
            MMA6(L[2*ntp], L[2*ntp+1], a2h[kg], a2l[kg], bh, bl);
        }
    }

    #pragma unroll
    for (int nt = 0; nt < 4; nt++) {
        int col = nt * 8 + 2 * tg;
        L[nt][0] += biaso[col];
        L[nt][1] += biaso[col + 1];
        L[nt][2] += biaso[col];
        L[nt][3] += biaso[col + 1];
        float2 o0; o0.x = L[nt][0]; o0.y = L[nt][1];
        float2 o1; o1.x = L[nt][2]; o1.y = L[nt][3];
        *(float2*)(out + (size_t)grow0 * 32 + col) = o0;
        *(float2*)(out + (size_t)grow1 * 32 + col) = o1;
    }

    float mx0 = -1e30f, mx1 = -1e30f;
    #pragma unroll
    for (int nt = 0; nt < 4; nt++) {
        mx0 = fmaxf(mx0, fmaxf(L[nt][0], L[nt][1]));
        mx1 = fmaxf(mx1, fmaxf(L[nt][2], L[nt][3]));
    }
    mx0 = fmaxf(mx0, __shfl_xor_sync(0xffffffffu, mx0, 1));
    mx0 = fmaxf(mx0, __shfl_xor_sync(0xffffffffu, mx0, 2));
    mx1 = fmaxf(mx1, __shfl_xor_sync(0xffffffffu, mx1, 1));
    mx1 = fmaxf(mx1, __shfl_xor_sync(0xffffffffu, mx1, 2));

    int t0 = tgt[grow0], t1 = tgt[grow1];
    float se0 = 0.f, se1 = 0.f, tv0 = -1e30f, tv1 = -1e30f;
    #pragma unroll
    for (int nt = 0; nt < 4; nt++) {
        int col = nt * 8 + 2 * tg;
        se0 += expf(L[nt][0] - mx0) + expf(L[nt][1] - mx0);
        se1 += expf(L[nt][2] - mx1) + expf(L[nt][3] - mx1);
        if (col == t0)     tv0 = L[nt][0];
        if (col + 1 == t0) tv0 = L[nt][1];
        if (col == t1)     tv1 = L[nt][2];
        if (col + 1 == t1) tv1 = L[nt][3];
    }
    se0 += __shfl_xor_sync(0xffffffffu, se0, 1);
    se0 += __shfl_xor_sync(0xffffffffu, se0, 2);
    se1 += __shfl_xor_sync(0xffffffffu, se1, 1);
    se1 += __shfl_xor_sync(0xffffffffu, se1, 2);
    tv0 = fmaxf(tv0, __shfl_xor_sync(0xffffffffu, tv0, 1));
    tv0 = fmaxf(tv0, __shfl_xor_sync(0xffffffffu, tv0, 2));
    tv1 = fmaxf(tv1, __shfl_xor_sync(0xffffffffu, tv1, 1));
    tv1 = fmaxf(tv1, __shfl_xor_sync(0xffffffffu, tv1, 2));

    if (tg == 0) {
        float nll0 = -(tv0 - mx0 - logf(se0));
        float nll1 = -(tv1 - mx1 - logf(se1));
        red[w * 8 + g] = nll0 + nll1;
    }
    __syncthreads();
    for (int s = 32; s > 0; s >>= 1) {
        if (tid < s) red[tid] += red[tid + s];
        __syncthreads();
    }
    if (tid == 0) g_losspart[blockIdx.x] = red[0];
}

// =============================================================================
// mma.sync bf16 flash attention with ldmatrix operand loads
// =============================================================================
__global__ void __launch_bounds__(256, 2) k_attn_mma() {
    int bid = blockIdx.x;
    int qt = 15 - (bid >> 6);
    int bh = bid & 63;
    int b = bh >> 3, h = bh & 7;
    int tid = threadIdx.x;
    int w = tid >> 5, lane = tid & 31;
    int g = lane >> 2, tg = lane & 3;
    int tokbase = b * Mm;
    int qBase = qt * 128 + w * 16;

    __shared__ __align__(16) uint32_t Khi[64*KP], Klo[64*KP];
    __shared__ __align__(16) uint32_t Vhi[64*KP], Vlo[64*KP];

    uint32_t qh[4], ql[4];
    {
        const uint32_t* ph = g_qh + (size_t)(tokbase + qBase) * 64 + h * 8;
        const uint32_t* pl = g_ql + (size_t)(tokbase + qBase) * 64 + h * 8;
        qh[0] = ph[(size_t)g * 64 + tg];
        qh[1] = ph[(size_t)(g + 8) * 64 + tg];
        qh[2] = ph[(size_t)g * 64 + tg + 4];
        qh[3] = ph[(size_t)(g + 8) * 64 + tg + 4];
        ql[0] = pl[(size_t)g * 64 + tg];
        ql[1] = pl[(size_t)(g + 8) * 64 + tg];
        ql[2] = pl[(size_t)g * 64 + tg + 4];
        ql[3] = pl[(size_t)(g + 8) * 64 + tg + 4];
    }

    int lrow = lane & 15;
    int lcol = (lane >> 4) * 4;
    uint32_t kvoff = ((uint32_t)lrow * KP + lcol) * 4;
    uint32_t adK_h = s_addr(Khi) + kvoff, adK_l = s_addr(Klo) + kvoff;
    uint32_t adV_h = s_addr(Vhi) + kvoff, adV_l = s_addr(Vlo) + kvoff;

    float o[2][4];
    #pragma unroll
    for (int t = 0; t < 2; t++)
        #pragma unroll
        for (int e = 0; e < 4; e++) o[t][e] = 0.f;
    float m0 = -1e30f, m1 = -1e30f, l0 = 0.f, l1 = 0.f;

    int q0 = qBase + g;
    int q1 = qBase + g + 8;

    int nkt = 2 * qt + 2;
    for (int kt = 0; kt < nkt; kt++) {
        int kb = kt * 64;
        __syncthreads();
        #pragma unroll
        for (int i = 0; i < 2; i++) {
            int wv = tid + i * 256;
            int key = wv >> 3, c = wv & 7;
            size_t ga = (size_t)(tokbase + kb + key) * 64 + h * 8 + c;
            Khi[key * KP + c] = g_kh[ga];
            Klo[key * KP + c] = g_kl[ga];
            Vhi[key * KP + c] = g_vh[ga];
            Vlo[key * KP + c] = g_vl[ga];
        }
        __syncthreads();

        // ---- S = Q K^T
        float s[8][4];
        #pragma unroll
        for (int ntp = 0; ntp < 4; ntp++) {
            #pragma unroll
            for (int e = 0; e < 4; e++) { s[2*ntp][e] = 0.f; s[2*ntp+1][e] = 0.f; }
            uint32_t bh_[4], bl_[4];
            ldsm4(bh_, adK_h + (uint32_t)ntp * (16 * KP * 4));
            ldsm4(bl_, adK_l + (uint32_t)ntp * (16 * KP * 4));
            MMA6(s[2*ntp], s[2*ntp+1], qh, ql, bh_, bl_);
        }

        // ---- mask + scale + row max
        float tmax0 = -1e30f, tmax1 = -1e30f;
        #pragma unroll
        for (int nt = 0; nt < 8; nt++) {
            int kc = kb + nt * 8 + 2 * tg;
            s[nt][0] = (kc     <= q0) ? s[nt][0] * 0.25f : -1e30f;
            s[nt][1] = (kc + 1 <= q0) ? s[nt][1] * 0.25f : -1e30f;
            s[nt][2] = (kc     <= q1) ? s[nt][2] * 0.25f : -1e30f;
            s[nt][3] = (kc + 1 <= q1) ? s[nt][3] * 0.25f : -1e30f;
            tmax0 = fmaxf(tmax0, fmaxf(s[nt][0], s[nt][1]));
            tmax1 = fmaxf(tmax1, fmaxf(s[nt][2], s[nt][3]));
        }
        tmax0 = fmaxf(tmax0, __shfl_xor_sync(0xffffffffu, tmax0, 1));
        tmax0 = fmaxf(tmax0, __shfl_xor_sync(0xffffffffu, tmax0, 2));
        tmax1 = fmaxf(tmax1, __shfl_xor_sync(0xffffffffu, tmax1, 1));
        tmax1 = fmaxf(tmax1, __shfl_xor_sync(0xffffffffu, tmax1, 2));

        float mn0 = fmaxf(m0, tmax0), mn1 = fmaxf(m1, tmax1);
        float a0 = __expf(m0 - mn0), a1 = __expf(m1 - mn1);
        m0 = mn0; m1 = mn1;
        l0 *= a0; l1 *= a1;
        #pragma unroll
        for (int t = 0; t < 2; t++) {
            o[t][0] *= a0; o[t][1] *= a0; o[t][2] *= a1; o[t][3] *= a1;
        }

        // ---- P = exp(S - m)
        uint32_t phi[8][2], plo[8][2];
        #pragma unroll
        for (int nt = 0; nt < 8; nt++) {
            float p0 = __expf(s[nt][0] - mn0);
            float p1 = __expf(s[nt][1] - mn0);
            float p2 = __expf(s[nt][2] - mn1);
            float p3 = __expf(s[nt][3] - mn1);
            l0 += p0 + p1; l1 += p2 + p3;
            bf16_split2(p0, p1, phi[nt][0], plo[nt][0]);
            bf16_split2(p2, p3, phi[nt][1], plo[nt][1]);
        }

        // ---- O += P V  (B frags via ldmatrix.trans on row-stored V)
        #pragma unroll
        for (int kg = 0; kg < 4; kg++) {
            uint32_t ah[4] = { phi[2*kg][0], phi[2*kg][1], phi[2*kg+1][0], phi[2*kg+1][1] };
            uint32_t al[4] = { plo[2*kg][0], plo[2*kg][1], plo[2*kg+1][0], plo[2*kg+1][1] };
            uint32_t bh_[4], bl_[4];
            ldsm4t(bh_, adV_h + (uint32_t)kg * (16 * KP * 4));
            ldsm4t(bl_, adV_l + (uint32_t)kg * (16 * KP * 4));
            // o[0]: b0=bh_[0] (keys lo, d 0-7), b1=bh_[1]; o[1]: bh_[2], bh_[3]
            mma_bf16(o[0], ah, bh_[0], bh_[1]);
            mma_bf16(o[0], al, bh_[0], bh_[1]);
            mma_bf16(o[0], ah, bl_[0], bl_[1]);
            mma_bf16(o[1], ah, bh_[2], bh_[3]);
            mma_bf16(o[1], al, bh_[2], bh_[3]);
            mma_bf16(o[1], ah, bl_[2], bl_[3]);
        }
    }

    l0 += __shfl_xor_sync(0xffffffffu, l0, 1);
    l0 += __shfl_xor_sync(0xffffffffu, l0, 2);
    l1 += __shfl_xor_sync(0xffffffffu, l1, 1);
    l1 += __shfl_xor_sync(0xffffffffu, l1, 2);
    float i0 = 1.f / l0, i1 = 1.f / l1;

    #pragma unroll
    for (int t = 0; t < 2; t++) {
        int d = h * HDIM + t * 8 + 2 * tg;
        float2 r0; r0.x = o[t][0] * i0; r0.y = o[t][1] * i0;
        float2 r1; r1.x = o[t][2] * i1; r1.y = o[t][3] * i1;
        *(float2*)(g_att + (size_t)(tokbase + q0) * 128 + d) = r0;
        *(float2*)(g_att + (size_t)(tokbase + q1) * 128 + d) = r1;
    }
}

// ----------------------------- small kernels ----------------------------------
__global__ void k_rope_tables() {
    int i   = threadIdx.x;
    int pos = blockIdx.x;
    float base = powf(10000.0f, -2.0f * ((float)i - 1.0f) / 128.0f);
    float ang  = (float)pos * base;
    float s, c;
    sincosf(ang, &s, &c);
    g_cos[pos*64 + i] = c;
    g_sin[pos*64 + i] = s;
}

__global__ void __launch_bounds__(256) k_embed(const int* __restrict__ idx,
                                               const float* __restrict__ emb) {
    int b   = blockIdx.x;
    int seg = blockIdx.y;
    int tid = threadIdx.x;
    int tok0 = seg * 16;
    float ss = 0.f;
    #pragma unroll
    for (int e = 0; e < 8; e++) {
        int li = tid + e * 256;
        int t  = tok0 + (li >> 7);
        int d  = li & 127;
        int row = idx[b*Mm + t];
        float vv = emb[row*Dd + d];
        g_x0[((size_t)(b*Mm + t))*Dd + d] = vv;
        ss += vv * vv;
    }
    __shared__ float red[256];
    red[tid] = ss; __syncthreads();
    for (int s = 128; s > 0; s >>= 1) {
        if (tid < s) red[tid] += red[tid + s];
        __syncthreads();
    }
    if (tid == 0) g_part[b*128 + seg] = red[0];
}

__global__ void k_inv() {
    int b = blockIdx.x;
    int tid = threadIdx.x;
    __shared__ float red[128];
    red[tid] = g_part[b*128 + tid]; __syncthreads();
    for (int s = 64; s > 0; s >>= 1) {
        if (tid < s) red[tid] += red[tid + s];
        __syncthreads();
    }
    if (tid == 0) g_inv[b] = 512.0f / sqrtf(red[0]);
}

__global__ void k_inv2() {
    int b = blockIdx.x;
    int tid = threadIdx.x;
    __shared__ float red[16];
    red[tid] = g_part2[b*16 + tid]; __syncthreads();
    for (int s = 8; s > 0; s >>= 1) {
        if (tid < s) red[tid] += red[tid + s];
        __syncthreads();
    }
    if (tid == 0) g_inv2[b] = 512.0f / sqrtf(red[0]);
}

__global__ void k_lossfin(float* out) {
    int tid = threadIdx.x;
    __shared__ float red[128];
    red[tid] = g_losspart[tid]; __syncthreads();
    for (int s = 64; s > 0; s >>= 1) {
        if (tid < s) red[tid] += red[tid + s];
        __syncthreads();
    }
    if (tid == 0) out[0] = red[0] / (float)TOK;
}

// ----------------------------- host driver -----------------------------------
extern "C" void kernel_launch(void* const* d_in, const int* in_sizes, int n_in,
                              void* d_out, int out_size) {
    const int*   idx = (const int*)  d_in[0];
    const int*   tgt = (const int*)  d_in[1];
    const float* emb = (const float*)d_in[2];
    const float* rms = (const float*)d_in[3];
    const float* Wq  = (const float*)d_in[4];
    const float* Wk  = (const float*)d_in[5];
    const float* Wv  = (const float*)d_in[6];
    const float* inw = (const float*)d_in[7];
    const float* inb = (const float*)d_in[8];
    const float* opw = (const float*)d_in[9];
    const float* opb = (const float*)d_in[10];
    const float* lw  = (const float*)d_in[11];
    const float* lb  = (const float*)d_in[12];
    const float* ow  = (const float*)d_in[13];
    const float* ob  = (const float*)d_in[14];
    float* out = (float*)d_out;

    float *x0, *att, *x1;
    uint32_t *qh, *ql, *kh, *kl, *vh, *vl;
    cudaGetSymbolAddress((void**)&x0,  g_x0);
    cudaGetSymbolAddress((void**)&att, g_att);
    cudaGetSymbolAddress((void**)&x1,  g_x1);
    cudaGetSymbolAddress((void**)&qh,  g_qh);
    cudaGetSymbolAddress((void**)&ql,  g_ql);
    cudaGetSymbolAddress((void**)&kh,  g_kh);
    cudaGetSymbolAddress((void**)&kl,  g_kl);
    cudaGetSymbolAddress((void**)&vh,  g_vh);
    cudaGetSymbolAddress((void**)&vl,  g_vl);

    const int PLANES = 4 * 128 * P * 4;
    const int SMQ = PLANES + 128 * 4;
    const int SMO = PLANES + 128 * 4 + 256 * 4;
    const int SMM = PLANES + 128 * 4 + 32 * 4 + 64 * 4;
    cudaFuncSetAttribute(k_qkv,   cudaFuncAttributeMaxDynamicSharedMemorySize, SMQ);
    cudaFuncSetAttribute(k_oproj, cudaFuncAttributeMaxDynamicSharedMemorySize, SMO);
    cudaFuncSetAttribute(k_mlp,   cudaFuncAttributeMaxDynamicSharedMemorySize, SMM);

    k_rope_tables<<<Mm, 64>>>();
    k_embed<<<dim3(Bb, 128), 256>>>(idx, emb);
    k_inv<<<Bb, 128>>>();

    k_qkv<<<dim3(128, 3), 256, SMQ>>>(x0, rms, Wq, Wk, Wv, inw, inb,
                                      qh, ql, kh, kl, vh, vl);

    k_attn_mma<<<1024, 256>>>();

    k_oproj<<<128, 256, SMO>>>(att, opw, opb, x0, rms, x1);
    k_inv2<<<Bb, 16>>>();

    k_mlp<<<128, 256, SMM>>>(x1, rms, lw, lb, ow, ob, tgt, out);

    if (out_size > TOK*Vv) k_lossfin<<<1, 128>>>(out + (size_t)TOK*Vv);
}